// round 1
// baseline (speedup 1.0000x reference)
#include <cuda_runtime.h>
#include <cuda_bf16.h>

// Problem constants
#define B_   2
#define N_   4096
#define INF_ 256
#define H_   4
#define F_   64
#define BN_  (B_ * N_)      // 8192
#define HF_  (H_ * F_)      // 256
#define MAXD 512            // max neighbors per row (mean ~82, +40 sigma headroom)

// ---------------- scratch (device globals; no allocation allowed) ----------
__device__ __align__(16) float g_h[BN_ * HF_];        // h = x @ W^T  [bn][head*64+f]
__device__ __align__(16) float g_ssrc[BN_ * H_];      // s_src [bn][h]
__device__ __align__(16) float g_sdst[BN_ * H_];      // s_dst [bn][h]
__device__ int   g_nbrs[N_ * MAXD];                   // CSR-ish neighbor lists
__device__ int   g_deg[N_];

// ---------------------------------------------------------------------------
// Kernel 1: h = x @ W^T   (M=8192, N=256, K=256), fp32 tiled GEMM
// BM=64, BN=64, BK=32, 256 threads, 4x4 register tile per thread.
// ---------------------------------------------------------------------------
__global__ __launch_bounds__(256) void gemm_kernel(const float* __restrict__ x,
                                                   const float* __restrict__ W)
{
    const int bm = blockIdx.x * 64;   // row tile   (over B*N)
    const int bo = blockIdx.y * 64;   // col tile   (over H*F)

    // smem tiles stored k-major, padded to 68 floats (16B aligned rows, fewer bank conflicts)
    __shared__ __align__(16) float As[32][68];
    __shared__ __align__(16) float Bs[32][68];

    const int t    = threadIdx.x;
    const int tx   = t & 15;          // 0..15 -> output col group
    const int ty   = t >> 4;          // 0..15 -> output row group
    const int lrow = t >> 2;          // 0..63 load row
    const int lk   = (t & 3) * 8;     // load col offset within BK (8 floats)

    float acc[4][4];
#pragma unroll
    for (int i = 0; i < 4; i++)
#pragma unroll
        for (int j = 0; j < 4; j++) acc[i][j] = 0.0f;

    for (int k0 = 0; k0 < INF_; k0 += 32) {
        // stage global -> registers (two float4 each for A and B)
        const float4* xg = reinterpret_cast<const float4*>(&x[(bm + lrow) * INF_ + k0 + lk]);
        float4 a0 = xg[0], a1 = xg[1];
        const float4* wg = reinterpret_cast<const float4*>(&W[(bo + lrow) * INF_ + k0 + lk]);
        float4 b0 = wg[0], b1 = wg[1];

        __syncthreads();   // previous iteration's compute done before overwrite
        As[lk + 0][lrow] = a0.x; As[lk + 1][lrow] = a0.y;
        As[lk + 2][lrow] = a0.z; As[lk + 3][lrow] = a0.w;
        As[lk + 4][lrow] = a1.x; As[lk + 5][lrow] = a1.y;
        As[lk + 6][lrow] = a1.z; As[lk + 7][lrow] = a1.w;
        Bs[lk + 0][lrow] = b0.x; Bs[lk + 1][lrow] = b0.y;
        Bs[lk + 2][lrow] = b0.z; Bs[lk + 3][lrow] = b0.w;
        Bs[lk + 4][lrow] = b1.x; Bs[lk + 5][lrow] = b1.y;
        Bs[lk + 6][lrow] = b1.z; Bs[lk + 7][lrow] = b1.w;
        __syncthreads();

#pragma unroll
        for (int kk = 0; kk < 32; kk++) {
            float4 av = *reinterpret_cast<const float4*>(&As[kk][ty * 4]);
            float4 bv = *reinterpret_cast<const float4*>(&Bs[kk][tx * 4]);
            float a[4] = {av.x, av.y, av.z, av.w};
            float b[4] = {bv.x, bv.y, bv.z, bv.w};
#pragma unroll
            for (int i = 0; i < 4; i++)
#pragma unroll
                for (int j = 0; j < 4; j++) acc[i][j] = fmaf(a[i], b[j], acc[i][j]);
        }
    }

#pragma unroll
    for (int i = 0; i < 4; i++) {
        const int row = bm + ty * 4 + i;
        float4 v = make_float4(acc[i][0], acc[i][1], acc[i][2], acc[i][3]);
        *reinterpret_cast<float4*>(&g_h[row * HF_ + bo + tx * 4]) = v;
    }
}

// ---------------------------------------------------------------------------
// Kernel 2: s_src[bn][h] = sum_f h[bn][h][f] * a_src[h][f]  (same for dst)
// One block per bn, 256 threads (head = t/64, f = t%64).
// ---------------------------------------------------------------------------
__global__ __launch_bounds__(256) void s_kernel(const float* __restrict__ a_src,
                                                const float* __restrict__ a_dst)
{
    const int bn = blockIdx.x;
    const int t = threadIdx.x;
    const int head = t >> 6;
    const int f = t & 63;

    const float v = g_h[bn * HF_ + t];
    float ps = v * a_src[head * F_ + f];
    float pd = v * a_dst[head * F_ + f];

#pragma unroll
    for (int o = 16; o > 0; o >>= 1) {
        ps += __shfl_down_sync(0xFFFFFFFFu, ps, o);
        pd += __shfl_down_sync(0xFFFFFFFFu, pd, o);
    }

    __shared__ float ss[8], sd[8];
    const int w = t >> 5;
    if ((t & 31) == 0) { ss[w] = ps; sd[w] = pd; }
    __syncthreads();
    if (t < H_) {
        g_ssrc[bn * H_ + t] = ss[2 * t] + ss[2 * t + 1];
        g_sdst[bn * H_ + t] = sd[2 * t] + sd[2 * t + 1];
    }
}

// ---------------------------------------------------------------------------
// Kernel 3: build neighbor lists from dense adjacency (one block per row).
// Order within a row doesn't matter (softmax sum is order-insensitive to 1e-3).
// ---------------------------------------------------------------------------
__global__ __launch_bounds__(256) void csr_kernel(const float* __restrict__ adj)
{
    const int n = blockIdx.x;
    __shared__ int cnt;
    if (threadIdx.x == 0) cnt = 0;
    __syncthreads();

    const float* row = adj + (long long)n * N_;
    for (int m = threadIdx.x; m < N_; m += blockDim.x) {
        if (row[m] != 0.0f) {
            int p = atomicAdd(&cnt, 1);
            if (p < MAXD) g_nbrs[n * MAXD + p] = m;
        }
    }
    __syncthreads();
    if (threadIdx.x == 0) g_deg[n] = cnt < MAXD ? cnt : MAXD;
}

// ---------------------------------------------------------------------------
// Kernel 4: sparse softmax + aggregation.
// Block = one (b, n). 4 warps, one head per warp.
// e_m = leaky_relu(s_src[b,n,h] + s_dst[b,m,h], 0.2) over neighbors m only
// (masked entries underflow to exactly 0 in the fp32 reference softmax).
// ---------------------------------------------------------------------------
__global__ __launch_bounds__(128) void attn_kernel(float* __restrict__ out)
{
    const int n = blockIdx.x;
    const int b = blockIdx.y;
    const int bn = b * N_ + n;

    __shared__ int   nb[MAXD];
    __shared__ float ew[H_][MAXD];

    const int t = threadIdx.x;
    const int w = t >> 5;          // head
    const int lane = t & 31;

    const int deg = g_deg[n];
    for (int i = t; i < deg; i += 128) nb[i] = g_nbrs[n * MAXD + i];
    __syncthreads();

    // ---- phase 1: logits + max (strided over neighbors)
    const float c = g_ssrc[bn * H_ + w];
    float mx = -3.0e38f;
    for (int i = lane; i < deg; i += 32) {
        const int m = nb[i];
        float e = c + g_sdst[(b * N_ + m) * H_ + w];
        e = (e > 0.0f) ? e : 0.2f * e;        // leaky_relu slope 0.2
        ew[w][i] = e;
        mx = fmaxf(mx, e);
    }
#pragma unroll
    for (int o = 16; o > 0; o >>= 1) mx = fmaxf(mx, __shfl_xor_sync(0xFFFFFFFFu, mx, o));

    // ---- phase 2: exp + sum (each lane revisits its own indices)
    float sum = 0.0f;
    for (int i = lane; i < deg; i += 32) {
        float p = __expf(ew[w][i] - mx);
        ew[w][i] = p;
        sum += p;
    }
#pragma unroll
    for (int o = 16; o > 0; o >>= 1) sum += __shfl_xor_sync(0xFFFFFFFFu, sum, o);
    const float inv = 1.0f / sum;

    __syncwarp();  // ew writes visible warp-wide before broadcast reads

    // ---- phase 3: weighted aggregation; each lane owns 2 f-values (float2)
    const float2* hb = reinterpret_cast<const float2*>(g_h);
    const int fbase = w * 32 + lane;   // float2 index within a head
    float2 acc = make_float2(0.0f, 0.0f);

    int i = 0;
    for (; i + 1 < deg; i += 2) {
        const float p0 = ew[w][i];
        const float p1 = ew[w][i + 1];
        const int m0 = nb[i];
        const int m1 = nb[i + 1];
        const float2 v0 = hb[(b * N_ + m0) * 128 + fbase];
        const float2 v1 = hb[(b * N_ + m1) * 128 + fbase];
        acc.x = fmaf(p0, v0.x, acc.x); acc.y = fmaf(p0, v0.y, acc.y);
        acc.x = fmaf(p1, v1.x, acc.x); acc.y = fmaf(p1, v1.y, acc.y);
    }
    if (i < deg) {
        const float p = ew[w][i];
        const int m = nb[i];
        const float2 v = hb[(b * N_ + m) * 128 + fbase];
        acc.x = fmaf(p, v.x, acc.x); acc.y = fmaf(p, v.y, acc.y);
    }

    float2 r = make_float2(acc.x * inv, acc.y * inv);
    reinterpret_cast<float2*>(out)[bn * 128 + fbase] = r;
}

// ---------------------------------------------------------------------------
extern "C" void kernel_launch(void* const* d_in, const int* in_sizes, int n_in,
                              void* d_out, int out_size)
{
    const float* x     = (const float*)d_in[0];
    const float* adj   = (const float*)d_in[1];
    const float* W     = (const float*)d_in[2];
    const float* a_src = (const float*)d_in[3];
    const float* a_dst = (const float*)d_in[4];
    float* out = (float*)d_out;

    gemm_kernel<<<dim3(BN_ / 64, HF_ / 64), 256>>>(x, W);
    s_kernel<<<BN_, 256>>>(a_src, a_dst);
    csr_kernel<<<N_, 256>>>(adj);
    attn_kernel<<<dim3(N_, B_), 128>>>(out);
}

// round 2
// speedup vs baseline: 1.1895x; 1.1895x over previous
#include <cuda_runtime.h>
#include <cuda_bf16.h>
#include <cuda_fp16.h>
#include <cstdint>

// Problem constants
#define B_   2
#define N_   4096
#define INF_ 256
#define H_   4
#define F_   64
#define BN_  (B_ * N_)      // 8192
#define HF_  (H_ * F_)      // 256
#define MAXD 512

// ---------------- scratch (device globals) ----------------------------------
__device__ __align__(16) float  g_h[BN_ * HF_];    // h fp32 (for s vectors)
__device__ __align__(16) __half g_h16[BN_ * HF_];  // h fp16 (for aggregation gather)
__device__ __align__(16) float  g_ssrc[BN_ * H_];
__device__ __align__(16) float  g_sdst[BN_ * H_];
__device__ int g_nbrs[N_ * MAXD];
__device__ int g_deg[N_];

// ---------------------------------------------------------------------------
// TF32 helpers
// ---------------------------------------------------------------------------
__device__ __forceinline__ float to_tf32(float a) {
    uint32_t u;
    asm("cvt.rna.tf32.f32 %0, %1;" : "=r"(u) : "f"(a));
    return __uint_as_float(u);
}

__device__ __forceinline__ void mma_tf32(float c[4],
                                         uint32_t a0, uint32_t a1, uint32_t a2, uint32_t a3,
                                         uint32_t b0, uint32_t b1)
{
    asm volatile(
        "mma.sync.aligned.m16n8k8.row.col.f32.tf32.tf32.f32 "
        "{%0,%1,%2,%3},{%4,%5,%6,%7},{%8,%9},{%0,%1,%2,%3};"
        : "+f"(c[0]), "+f"(c[1]), "+f"(c[2]), "+f"(c[3])
        : "r"(a0), "r"(a1), "r"(a2), "r"(a3), "r"(b0), "r"(b1));
}

// ---------------------------------------------------------------------------
// Kernel 1: h = x @ W^T via TF32 tensor cores.
// Block tile 128x64, BK=32, 256 threads = 8 warps in 2(m) x 4(n) grid.
// Warp tile 64x16 = 4 m-tiles x 2 n-tiles of m16n8k8.
// smem padded to stride 36 floats -> conflict-free fragment LDS
// (bank = 4*row + col mod 32, distinct across lanes).
// Writes h in fp32 and fp16.
// ---------------------------------------------------------------------------
#define GBM 128
#define GBN 64
#define GBK 32
#define GPAD 36

__global__ __launch_bounds__(256) void gemm_tf32(const float* __restrict__ x,
                                                 const float* __restrict__ W)
{
    const int bm = blockIdx.x * GBM;
    const int bo = blockIdx.y * GBN;

    __shared__ float As[GBM][GPAD];
    __shared__ float Bs[GBN][GPAD];

    const int t    = threadIdx.x;
    const int lane = t & 31;
    const int warp = t >> 5;
    const int wm   = warp >> 2;   // 0..1
    const int wn   = warp & 3;    // 0..3

    float acc[4][2][4];
#pragma unroll
    for (int mt = 0; mt < 4; mt++)
#pragma unroll
        for (int nt = 0; nt < 2; nt++)
#pragma unroll
            for (int i = 0; i < 4; i++) acc[mt][nt][i] = 0.0f;

    for (int k0 = 0; k0 < INF_; k0 += GBK) {
        // global -> registers (A: 4x float4, B: 2x float4), convert to tf32
        float4 ar[4], br[2];
#pragma unroll
        for (int j = 0; j < 4; j++) {
            int v = t + 256 * j;           // float4 index into 128x32 tile
            int row = v >> 3;
            int col = (v & 7) * 4;
            ar[j] = *reinterpret_cast<const float4*>(&x[(long long)(bm + row) * INF_ + k0 + col]);
        }
#pragma unroll
        for (int j = 0; j < 2; j++) {
            int v = t + 256 * j;           // float4 index into 64x32 tile
            int row = v >> 3;
            int col = (v & 7) * 4;
            br[j] = *reinterpret_cast<const float4*>(&W[(long long)(bo + row) * INF_ + k0 + col]);
        }

        __syncthreads();
#pragma unroll
        for (int j = 0; j < 4; j++) {
            int v = t + 256 * j;
            int row = v >> 3;
            int col = (v & 7) * 4;
            As[row][col + 0] = to_tf32(ar[j].x);
            As[row][col + 1] = to_tf32(ar[j].y);
            As[row][col + 2] = to_tf32(ar[j].z);
            As[row][col + 3] = to_tf32(ar[j].w);
        }
#pragma unroll
        for (int j = 0; j < 2; j++) {
            int v = t + 256 * j;
            int row = v >> 3;
            int col = (v & 7) * 4;
            Bs[row][col + 0] = to_tf32(br[j].x);
            Bs[row][col + 1] = to_tf32(br[j].y);
            Bs[row][col + 2] = to_tf32(br[j].z);
            Bs[row][col + 3] = to_tf32(br[j].w);
        }
        __syncthreads();

#pragma unroll
        for (int ks = 0; ks < 4; ks++) {
            const int kc = ks * 8 + (lane & 3);
            uint32_t Af[4][4];
#pragma unroll
            for (int mt = 0; mt < 4; mt++) {
                const int r0 = wm * 64 + mt * 16 + (lane >> 2);
                Af[mt][0] = __float_as_uint(As[r0][kc]);
                Af[mt][1] = __float_as_uint(As[r0 + 8][kc]);
                Af[mt][2] = __float_as_uint(As[r0][kc + 4]);
                Af[mt][3] = __float_as_uint(As[r0 + 8][kc + 4]);
            }
            uint32_t Bf[2][2];
#pragma unroll
            for (int nt = 0; nt < 2; nt++) {
                const int n0 = wn * 16 + nt * 8 + (lane >> 2);
                Bf[nt][0] = __float_as_uint(Bs[n0][kc]);
                Bf[nt][1] = __float_as_uint(Bs[n0][kc + 4]);
            }
#pragma unroll
            for (int mt = 0; mt < 4; mt++)
#pragma unroll
                for (int nt = 0; nt < 2; nt++)
                    mma_tf32(acc[mt][nt], Af[mt][0], Af[mt][1], Af[mt][2], Af[mt][3],
                             Bf[nt][0], Bf[nt][1]);
        }
    }

    // epilogue: fp32 + fp16 stores
#pragma unroll
    for (int mt = 0; mt < 4; mt++) {
#pragma unroll
        for (int nt = 0; nt < 2; nt++) {
            const int row = bm + wm * 64 + mt * 16 + (lane >> 2);
            const int col = bo + wn * 16 + nt * 8 + (lane & 3) * 2;
            float2 v0 = make_float2(acc[mt][nt][0], acc[mt][nt][1]);
            float2 v1 = make_float2(acc[mt][nt][2], acc[mt][nt][3]);
            *reinterpret_cast<float2*>(&g_h[(long long)row * HF_ + col]) = v0;
            *reinterpret_cast<float2*>(&g_h[(long long)(row + 8) * HF_ + col]) = v1;
            *reinterpret_cast<__half2*>(&g_h16[(long long)row * HF_ + col]) = __float22half2_rn(v0);
            *reinterpret_cast<__half2*>(&g_h16[(long long)(row + 8) * HF_ + col]) = __float22half2_rn(v1);
        }
    }
}

// ---------------------------------------------------------------------------
// Kernel 2: s_src / s_dst
// ---------------------------------------------------------------------------
__global__ __launch_bounds__(256) void s_kernel(const float* __restrict__ a_src,
                                                const float* __restrict__ a_dst)
{
    const int bn = blockIdx.x;
    const int t = threadIdx.x;
    const int head = t >> 6;
    const int f = t & 63;

    const float v = g_h[bn * HF_ + t];
    float ps = v * a_src[head * F_ + f];
    float pd = v * a_dst[head * F_ + f];

#pragma unroll
    for (int o = 16; o > 0; o >>= 1) {
        ps += __shfl_down_sync(0xFFFFFFFFu, ps, o);
        pd += __shfl_down_sync(0xFFFFFFFFu, pd, o);
    }

    __shared__ float ss[8], sd[8];
    const int w = t >> 5;
    if ((t & 31) == 0) { ss[w] = ps; sd[w] = pd; }
    __syncthreads();
    if (t < H_) {
        g_ssrc[bn * H_ + t] = ss[2 * t] + ss[2 * t + 1];
        g_sdst[bn * H_ + t] = sd[2 * t] + sd[2 * t + 1];
    }
}

// ---------------------------------------------------------------------------
// Kernel 3: neighbor lists from dense adjacency (float4 reads; DRAM-bound)
// ---------------------------------------------------------------------------
__global__ __launch_bounds__(256) void csr_kernel(const float* __restrict__ adj)
{
    const int n = blockIdx.x;
    __shared__ int cnt;
    if (threadIdx.x == 0) cnt = 0;
    __syncthreads();

    const float4* row4 = reinterpret_cast<const float4*>(adj + (long long)n * N_);
    for (int i = threadIdx.x; i < N_ / 4; i += 256) {
        float4 v = row4[i];
        if (v.x != 0.0f) { int p = atomicAdd(&cnt, 1); if (p < MAXD) g_nbrs[n * MAXD + p] = i * 4 + 0; }
        if (v.y != 0.0f) { int p = atomicAdd(&cnt, 1); if (p < MAXD) g_nbrs[n * MAXD + p] = i * 4 + 1; }
        if (v.z != 0.0f) { int p = atomicAdd(&cnt, 1); if (p < MAXD) g_nbrs[n * MAXD + p] = i * 4 + 2; }
        if (v.w != 0.0f) { int p = atomicAdd(&cnt, 1); if (p < MAXD) g_nbrs[n * MAXD + p] = i * 4 + 3; }
    }
    __syncthreads();
    if (threadIdx.x == 0) g_deg[n] = cnt < MAXD ? cnt : MAXD;
}

// ---------------------------------------------------------------------------
// Kernel 4: sparse softmax + aggregation. Block = (b,n); warp = head.
// Aggregation gathers fp16 h rows (128B per head-row -> 1 L1 wavefront).
// ---------------------------------------------------------------------------
__global__ __launch_bounds__(128) void attn_kernel(float* __restrict__ out)
{
    const int n = blockIdx.x;
    const int b = blockIdx.y;
    const int bn = b * N_ + n;

    __shared__ int   nb[MAXD];
    __shared__ float ew[H_][MAXD];

    const int t = threadIdx.x;
    const int w = t >> 5;
    const int lane = t & 31;

    const int deg = g_deg[n];
    for (int i = t; i < deg; i += 128) nb[i] = g_nbrs[n * MAXD + i];
    __syncthreads();

    // phase 1: logits + max
    const float c = g_ssrc[bn * H_ + w];
    float mx = -3.0e38f;
    for (int i = lane; i < deg; i += 32) {
        const int m = nb[i];
        float e = c + g_sdst[(b * N_ + m) * H_ + w];
        e = (e > 0.0f) ? e : 0.2f * e;
        ew[w][i] = e;
        mx = fmaxf(mx, e);
    }
#pragma unroll
    for (int o = 16; o > 0; o >>= 1) mx = fmaxf(mx, __shfl_xor_sync(0xFFFFFFFFu, mx, o));

    // phase 2: exp + sum
    float sum = 0.0f;
    for (int i = lane; i < deg; i += 32) {
        float p = __expf(ew[w][i] - mx);
        ew[w][i] = p;
        sum += p;
    }
#pragma unroll
    for (int o = 16; o > 0; o >>= 1) sum += __shfl_xor_sync(0xFFFFFFFFu, sum, o);
    const float inv = 1.0f / sum;

    __syncwarp();

    // phase 3: weighted aggregation over fp16 h; lane owns one half2 (2 f-values)
    const __half2* hb = reinterpret_cast<const __half2*>(g_h16);
    const int fbase = w * 32 + lane;   // half2 index within row (128 half2 per row)
    float2 acc = make_float2(0.0f, 0.0f);

    int i = 0;
    for (; i + 1 < deg; i += 2) {
        const float p0 = ew[w][i];
        const float p1 = ew[w][i + 1];
        const int m0 = nb[i];
        const int m1 = nb[i + 1];
        const float2 v0 = __half22float2(hb[(long long)(b * N_ + m0) * 128 + fbase]);
        const float2 v1 = __half22float2(hb[(long long)(b * N_ + m1) * 128 + fbase]);
        acc.x = fmaf(p0, v0.x, acc.x); acc.y = fmaf(p0, v0.y, acc.y);
        acc.x = fmaf(p1, v1.x, acc.x); acc.y = fmaf(p1, v1.y, acc.y);
    }
    if (i < deg) {
        const float p = ew[w][i];
        const int m = nb[i];
        const float2 v = __half22float2(hb[(long long)(b * N_ + m) * 128 + fbase]);
        acc.x = fmaf(p, v.x, acc.x); acc.y = fmaf(p, v.y, acc.y);
    }

    float2 r = make_float2(acc.x * inv, acc.y * inv);
    reinterpret_cast<float2*>(out)[bn * 128 + fbase] = r;
}

// ---------------------------------------------------------------------------
extern "C" void kernel_launch(void* const* d_in, const int* in_sizes, int n_in,
                              void* d_out, int out_size)
{
    const float* x     = (const float*)d_in[0];
    const float* adj   = (const float*)d_in[1];
    const float* W     = (const float*)d_in[2];
    const float* a_src = (const float*)d_in[3];
    const float* a_dst = (const float*)d_in[4];
    float* out = (float*)d_out;

    gemm_tf32<<<dim3(BN_ / GBM, HF_ / GBN), 256>>>(x, W);
    s_kernel<<<BN_, 256>>>(a_src, a_dst);
    csr_kernel<<<N_, 256>>>(adj);
    attn_kernel<<<dim3(N_, B_), 128>>>(out);
}

// round 3
// speedup vs baseline: 1.4101x; 1.1854x over previous
#include <cuda_runtime.h>
#include <cuda_bf16.h>
#include <cuda_fp16.h>
#include <cstdint>

#define B_   2
#define N_   4096
#define INF_ 256
#define H_   4
#define F_   64
#define BN_  (B_ * N_)      // 8192
#define HF_  (H_ * F_)      // 256
#define MAXD   512          // global neighbor-list stride
#define MAXD_S 320          // smem capacity (deg mean ~82, sigma ~9 -> 26 sigma margin)

// ---------------- scratch (device globals) ----------------------------------
__device__ __align__(16) float  g_h[BN_ * HF_];    // h fp32 (feeds s vectors)
__device__ __align__(16) __half g_h16[BN_ * HF_];  // h fp16 (aggregation gather)
__device__ __align__(16) float  g_ssrc[BN_ * H_];  // [bn][4] -> float4 rows
__device__ __align__(16) float  g_sdst[BN_ * H_];
__device__ int g_nbrs[N_ * MAXD];
__device__ int g_deg[N_];

// ---------------------------------------------------------------------------
// TF32 helpers
// ---------------------------------------------------------------------------
__device__ __forceinline__ float to_tf32(float a) {
    uint32_t u;
    asm("cvt.rna.tf32.f32 %0, %1;" : "=r"(u) : "f"(a));
    return __uint_as_float(u);
}

__device__ __forceinline__ void mma_tf32(float c[4],
                                         uint32_t a0, uint32_t a1, uint32_t a2, uint32_t a3,
                                         uint32_t b0, uint32_t b1)
{
    asm volatile(
        "mma.sync.aligned.m16n8k8.row.col.f32.tf32.tf32.f32 "
        "{%0,%1,%2,%3},{%4,%5,%6,%7},{%8,%9},{%0,%1,%2,%3};"
        : "+f"(c[0]), "+f"(c[1]), "+f"(c[2]), "+f"(c[3])
        : "r"(a0), "r"(a1), "r"(a2), "r"(a3), "r"(b0), "r"(b1));
}

// ---------------------------------------------------------------------------
// Kernel 1: h = x @ W^T via TF32 tensor cores (unchanged from R2).
// ---------------------------------------------------------------------------
#define GBM 128
#define GBN 64
#define GBK 32
#define GPAD 36

__global__ __launch_bounds__(256) void gemm_tf32(const float* __restrict__ x,
                                                 const float* __restrict__ W)
{
    const int bm = blockIdx.x * GBM;
    const int bo = blockIdx.y * GBN;

    __shared__ float As[GBM][GPAD];
    __shared__ float Bs[GBN][GPAD];

    const int t    = threadIdx.x;
    const int lane = t & 31;
    const int warp = t >> 5;
    const int wm   = warp >> 2;
    const int wn   = warp & 3;

    float acc[4][2][4];
#pragma unroll
    for (int mt = 0; mt < 4; mt++)
#pragma unroll
        for (int nt = 0; nt < 2; nt++)
#pragma unroll
            for (int i = 0; i < 4; i++) acc[mt][nt][i] = 0.0f;

    for (int k0 = 0; k0 < INF_; k0 += GBK) {
        float4 ar[4], br[2];
#pragma unroll
        for (int j = 0; j < 4; j++) {
            int v = t + 256 * j;
            int row = v >> 3;
            int col = (v & 7) * 4;
            ar[j] = *reinterpret_cast<const float4*>(&x[(bm + row) * INF_ + k0 + col]);
        }
#pragma unroll
        for (int j = 0; j < 2; j++) {
            int v = t + 256 * j;
            int row = v >> 3;
            int col = (v & 7) * 4;
            br[j] = *reinterpret_cast<const float4*>(&W[(bo + row) * INF_ + k0 + col]);
        }

        __syncthreads();
#pragma unroll
        for (int j = 0; j < 4; j++) {
            int v = t + 256 * j;
            int row = v >> 3;
            int col = (v & 7) * 4;
            As[row][col + 0] = to_tf32(ar[j].x);
            As[row][col + 1] = to_tf32(ar[j].y);
            As[row][col + 2] = to_tf32(ar[j].z);
            As[row][col + 3] = to_tf32(ar[j].w);
        }
#pragma unroll
        for (int j = 0; j < 2; j++) {
            int v = t + 256 * j;
            int row = v >> 3;
            int col = (v & 7) * 4;
            Bs[row][col + 0] = to_tf32(br[j].x);
            Bs[row][col + 1] = to_tf32(br[j].y);
            Bs[row][col + 2] = to_tf32(br[j].z);
            Bs[row][col + 3] = to_tf32(br[j].w);
        }
        __syncthreads();

#pragma unroll
        for (int ks = 0; ks < 4; ks++) {
            const int kc = ks * 8 + (lane & 3);
            uint32_t Af[4][4];
#pragma unroll
            for (int mt = 0; mt < 4; mt++) {
                const int r0 = wm * 64 + mt * 16 + (lane >> 2);
                Af[mt][0] = __float_as_uint(As[r0][kc]);
                Af[mt][1] = __float_as_uint(As[r0 + 8][kc]);
                Af[mt][2] = __float_as_uint(As[r0][kc + 4]);
                Af[mt][3] = __float_as_uint(As[r0 + 8][kc + 4]);
            }
            uint32_t Bf[2][2];
#pragma unroll
            for (int nt = 0; nt < 2; nt++) {
                const int n0 = wn * 16 + nt * 8 + (lane >> 2);
                Bf[nt][0] = __float_as_uint(Bs[n0][kc]);
                Bf[nt][1] = __float_as_uint(Bs[n0][kc + 4]);
            }
#pragma unroll
            for (int mt = 0; mt < 4; mt++)
#pragma unroll
                for (int nt = 0; nt < 2; nt++)
                    mma_tf32(acc[mt][nt], Af[mt][0], Af[mt][1], Af[mt][2], Af[mt][3],
                             Bf[nt][0], Bf[nt][1]);
        }
    }

#pragma unroll
    for (int mt = 0; mt < 4; mt++) {
#pragma unroll
        for (int nt = 0; nt < 2; nt++) {
            const int row = bm + wm * 64 + mt * 16 + (lane >> 2);
            const int col = bo + wn * 16 + nt * 8 + (lane & 3) * 2;
            float2 v0 = make_float2(acc[mt][nt][0], acc[mt][nt][1]);
            float2 v1 = make_float2(acc[mt][nt][2], acc[mt][nt][3]);
            *reinterpret_cast<float2*>(&g_h[row * HF_ + col]) = v0;
            *reinterpret_cast<float2*>(&g_h[(row + 8) * HF_ + col]) = v1;
            *reinterpret_cast<__half2*>(&g_h16[row * HF_ + col]) = __float22half2_rn(v0);
            *reinterpret_cast<__half2*>(&g_h16[(row + 8) * HF_ + col]) = __float22half2_rn(v1);
        }
    }
}

// ---------------------------------------------------------------------------
// Kernel 2: s_src / s_dst (from fp32 h)
// ---------------------------------------------------------------------------
__global__ __launch_bounds__(256) void s_kernel(const float* __restrict__ a_src,
                                                const float* __restrict__ a_dst)
{
    const int bn = blockIdx.x;
    const int t = threadIdx.x;
    const int head = t >> 6;
    const int f = t & 63;

    const float v = g_h[bn * HF_ + t];
    float ps = v * a_src[head * F_ + f];
    float pd = v * a_dst[head * F_ + f];

#pragma unroll
    for (int o = 16; o > 0; o >>= 1) {
        ps += __shfl_down_sync(0xFFFFFFFFu, ps, o);
        pd += __shfl_down_sync(0xFFFFFFFFu, pd, o);
    }

    __shared__ float ss[8], sd[8];
    const int w = t >> 5;
    if ((t & 31) == 0) { ss[w] = ps; sd[w] = pd; }
    __syncthreads();
    if (t < H_) {
        g_ssrc[bn * H_ + t] = ss[2 * t] + ss[2 * t + 1];
        g_sdst[bn * H_ + t] = sd[2 * t] + sd[2 * t + 1];
    }
}

// ---------------------------------------------------------------------------
// Kernel 3: neighbor lists from dense adjacency
// ---------------------------------------------------------------------------
__global__ __launch_bounds__(256) void csr_kernel(const float* __restrict__ adj)
{
    const int n = blockIdx.x;
    __shared__ int cnt;
    if (threadIdx.x == 0) cnt = 0;
    __syncthreads();

    const float4* row4 = reinterpret_cast<const float4*>(adj + (long long)n * N_);
    for (int i = threadIdx.x; i < N_ / 4; i += 256) {
        float4 v = row4[i];
        if (v.x != 0.0f) { int p = atomicAdd(&cnt, 1); if (p < MAXD) g_nbrs[n * MAXD + p] = i * 4 + 0; }
        if (v.y != 0.0f) { int p = atomicAdd(&cnt, 1); if (p < MAXD) g_nbrs[n * MAXD + p] = i * 4 + 1; }
        if (v.z != 0.0f) { int p = atomicAdd(&cnt, 1); if (p < MAXD) g_nbrs[n * MAXD + p] = i * 4 + 2; }
        if (v.w != 0.0f) { int p = atomicAdd(&cnt, 1); if (p < MAXD) g_nbrs[n * MAXD + p] = i * 4 + 3; }
    }
    __syncthreads();
    if (threadIdx.x == 0) g_deg[n] = cnt < MAXD ? cnt : MAXD;
}

// ---------------------------------------------------------------------------
// Kernel 4 (v3): one warp per (b,n) handles ALL 4 heads + full 512B fp16 row.
// Block = 4 warps = {b0,b1} x {n0,n1}; nb shared per n.
// Softmax without max-subtraction (|logit| <= ~10, exp safe in fp32; matches
// jax softmax which is shift-invariant).
// ---------------------------------------------------------------------------
__global__ __launch_bounds__(128) void attn_kernel(float* __restrict__ out)
{
    __shared__ int    nbS[2][MAXD_S];
    __shared__ float4 ewS[4][MAXD_S];
    __shared__ int    degS[2];

    const int t    = threadIdx.x;
    const int w    = t >> 5;        // warp 0..3
    const int lane = t & 31;
    const int b    = w & 1;
    const int nsub = w >> 1;
    const int n    = blockIdx.x * 2 + nsub;
    const int bn   = b * N_ + n;

    // warps with b==0 load the shared neighbor list for their n
    if (b == 0) {
        if (lane == 0) degS[nsub] = g_deg[n];
        const int dg = g_deg[n];
        for (int i = lane; i < dg && i < MAXD_S; i += 32)
            nbS[nsub][i] = g_nbrs[n * MAXD + i];
    }
    __syncthreads();

    const int deg = degS[nsub];
    const int degc = deg < MAXD_S ? deg : MAXD_S;   // smem-resident portion
    const int bN = b * N_;

    // ---- pass 1: p = exp(leaky_relu(s_src + s_dst)) for 4 heads; sum
    const float4 c4 = *reinterpret_cast<const float4*>(&g_ssrc[bn * H_]);
    const float4* sd4 = reinterpret_cast<const float4*>(g_sdst);

    float4 sum4 = make_float4(0.f, 0.f, 0.f, 0.f);
    for (int i = lane; i < degc; i += 32) {
        const int m = nbS[nsub][i];
        float4 sd = sd4[bN + m];
        float ex = c4.x + sd.x, ey = c4.y + sd.y, ez = c4.z + sd.z, ew = c4.w + sd.w;
        ex = (ex > 0.f) ? ex : 0.2f * ex;
        ey = (ey > 0.f) ? ey : 0.2f * ey;
        ez = (ez > 0.f) ? ez : 0.2f * ez;
        ew = (ew > 0.f) ? ew : 0.2f * ew;
        float4 p = make_float4(__expf(ex), __expf(ey), __expf(ez), __expf(ew));
        ewS[w][i] = p;
        sum4.x += p.x; sum4.y += p.y; sum4.z += p.z; sum4.w += p.w;
    }
    // tail beyond smem capacity (statistically never; correctness guard)
    for (int i = degc + lane; i < deg; i += 32) {
        const int m = g_nbrs[n * MAXD + i];
        float4 sd = sd4[bN + m];
        float ex = c4.x + sd.x, ey = c4.y + sd.y, ez = c4.z + sd.z, ew = c4.w + sd.w;
        ex = (ex > 0.f) ? ex : 0.2f * ex;
        ey = (ey > 0.f) ? ey : 0.2f * ey;
        ez = (ez > 0.f) ? ez : 0.2f * ez;
        ew = (ew > 0.f) ? ew : 0.2f * ew;
        sum4.x += __expf(ex); sum4.y += __expf(ey); sum4.z += __expf(ez); sum4.w += __expf(ew);
    }
#pragma unroll
    for (int o = 16; o > 0; o >>= 1) {
        sum4.x += __shfl_xor_sync(0xFFFFFFFFu, sum4.x, o);
        sum4.y += __shfl_xor_sync(0xFFFFFFFFu, sum4.y, o);
        sum4.z += __shfl_xor_sync(0xFFFFFFFFu, sum4.z, o);
        sum4.w += __shfl_xor_sync(0xFFFFFFFFu, sum4.w, o);
    }

    const int head = lane >> 3;     // 8 lanes per head; lane owns 8 halves (16B)
    float invh = (head & 2) ? ((head & 1) ? sum4.w : sum4.z)
                            : ((head & 1) ? sum4.y : sum4.x);
    invh = 1.0f / invh;

    __syncwarp();

    // ---- pass 2: aggregation. Whole warp walks neighbors together; each lane
    // loads its 16B chunk of the 512B fp16 row (1 LDG.128 per row per warp).
    const uint4* hrow = reinterpret_cast<const uint4*>(g_h16);
    const float* ewF = reinterpret_cast<const float*>(&ewS[w][0]);

    float2 a0 = make_float2(0.f, 0.f), a1 = a0, a2 = a0, a3 = a0;

    int i = 0;
    for (; i + 2 <= degc; i += 2) {
        const int  m0 = nbS[nsub][i];
        const int  m1 = nbS[nsub][i + 1];
        const float p0 = ewF[i * 4 + head];
        const float p1 = ewF[(i + 1) * 4 + head];
        const uint4 v0 = hrow[(bN + m0) * 32 + lane];
        const uint4 v1 = hrow[(bN + m1) * 32 + lane];

        float2 f;
        f = __half22float2(*reinterpret_cast<const __half2*>(&v0.x));
        a0.x = fmaf(p0, f.x, a0.x); a0.y = fmaf(p0, f.y, a0.y);
        f = __half22float2(*reinterpret_cast<const __half2*>(&v0.y));
        a1.x = fmaf(p0, f.x, a1.x); a1.y = fmaf(p0, f.y, a1.y);
        f = __half22float2(*reinterpret_cast<const __half2*>(&v0.z));
        a2.x = fmaf(p0, f.x, a2.x); a2.y = fmaf(p0, f.y, a2.y);
        f = __half22float2(*reinterpret_cast<const __half2*>(&v0.w));
        a3.x = fmaf(p0, f.x, a3.x); a3.y = fmaf(p0, f.y, a3.y);

        f = __half22float2(*reinterpret_cast<const __half2*>(&v1.x));
        a0.x = fmaf(p1, f.x, a0.x); a0.y = fmaf(p1, f.y, a0.y);
        f = __half22float2(*reinterpret_cast<const __half2*>(&v1.y));
        a1.x = fmaf(p1, f.x, a1.x); a1.y = fmaf(p1, f.y, a1.y);
        f = __half22float2(*reinterpret_cast<const __half2*>(&v1.z));
        a2.x = fmaf(p1, f.x, a2.x); a2.y = fmaf(p1, f.y, a2.y);
        f = __half22float2(*reinterpret_cast<const __half2*>(&v1.w));
        a3.x = fmaf(p1, f.x, a3.x); a3.y = fmaf(p1, f.y, a3.y);
    }
    if (i < degc) {
        const int  m0 = nbS[nsub][i];
        const float p0 = ewF[i * 4 + head];
        const uint4 v0 = hrow[(bN + m0) * 32 + lane];
        float2 f;
        f = __half22float2(*reinterpret_cast<const __half2*>(&v0.x));
        a0.x = fmaf(p0, f.x, a0.x); a0.y = fmaf(p0, f.y, a0.y);
        f = __half22float2(*reinterpret_cast<const __half2*>(&v0.y));
        a1.x = fmaf(p0, f.x, a1.x); a1.y = fmaf(p0, f.y, a1.y);
        f = __half22float2(*reinterpret_cast<const __half2*>(&v0.z));
        a2.x = fmaf(p0, f.x, a2.x); a2.y = fmaf(p0, f.y, a2.y);
        f = __half22float2(*reinterpret_cast<const __half2*>(&v0.w));
        a3.x = fmaf(p0, f.x, a3.x); a3.y = fmaf(p0, f.y, a3.y);
        i++;
    }
    // tail beyond smem capacity: recompute p on the fly
    for (; i < deg; i++) {
        const int m0 = g_nbrs[n * MAXD + i];
        float4 sd = sd4[bN + m0];
        float e = ((head & 2) ? ((head & 1) ? c4.w + sd.w : c4.z + sd.z)
                              : ((head & 1) ? c4.y + sd.y : c4.x + sd.x));
        e = (e > 0.f) ? e : 0.2f * e;
        const float p0 = __expf(e);
        const uint4 v0 = hrow[(bN + m0) * 32 + lane];
        float2 f;
        f = __half22float2(*reinterpret_cast<const __half2*>(&v0.x));
        a0.x = fmaf(p0, f.x, a0.x); a0.y = fmaf(p0, f.y, a0.y);
        f = __half22float2(*reinterpret_cast<const __half2*>(&v0.y));
        a1.x = fmaf(p0, f.x, a1.x); a1.y = fmaf(p0, f.y, a1.y);
        f = __half22float2(*reinterpret_cast<const __half2*>(&v0.z));
        a2.x = fmaf(p0, f.x, a2.x); a2.y = fmaf(p0, f.y, a2.y);
        f = __half22float2(*reinterpret_cast<const __half2*>(&v0.w));
        a3.x = fmaf(p0, f.x, a3.x); a3.y = fmaf(p0, f.y, a3.y);
    }

    // ---- store: lane owns 8 consecutive floats of the output row
    float4 o0 = make_float4(a0.x * invh, a0.y * invh, a1.x * invh, a1.y * invh);
    float4 o1 = make_float4(a2.x * invh, a2.y * invh, a3.x * invh, a3.y * invh);
    float4* outp = reinterpret_cast<float4*>(out);
    outp[bn * 64 + lane * 2 + 0] = o0;
    outp[bn * 64 + lane * 2 + 1] = o1;
}

// ---------------------------------------------------------------------------
extern "C" void kernel_launch(void* const* d_in, const int* in_sizes, int n_in,
                              void* d_out, int out_size)
{
    const float* x     = (const float*)d_in[0];
    const float* adj   = (const float*)d_in[1];
    const float* W     = (const float*)d_in[2];
    const float* a_src = (const float*)d_in[3];
    const float* a_dst = (const float*)d_in[4];
    float* out = (float*)d_out;

    gemm_tf32<<<dim3(BN_ / GBM, HF_ / GBN), 256>>>(x, W);
    s_kernel<<<BN_, 256>>>(a_src, a_dst);
    csr_kernel<<<N_, 256>>>(adj);
    attn_kernel<<<N_ / 2, 128>>>(out);
}

// round 4
// speedup vs baseline: 1.4775x; 1.0478x over previous
#include <cuda_runtime.h>
#include <cuda_bf16.h>
#include <cuda_fp16.h>
#include <cstdint>

#define B_   2
#define N_   4096
#define INF_ 256
#define H_   4
#define F_   64
#define BN_  (B_ * N_)      // 8192
#define HF_  (H_ * F_)      // 256
#define MAXD   512          // global neighbor-list stride
#define MAXD_S 320          // smem neighbor capacity (deg mean ~82, max ~125)

// ---------------- scratch (device globals) ----------------------------------
__device__ __align__(16) __half g_h16[BN_ * HF_];  // h fp16 (aggregation gather)
__device__ __align__(16) float  g_ssrc[BN_ * H_];  // [bn][4]
__device__ __align__(16) float  g_sdst[BN_ * H_];
__device__ int g_nbrs[N_ * MAXD];
__device__ int g_deg[N_];

// ---------------------------------------------------------------------------
// TF32 helpers
// ---------------------------------------------------------------------------
__device__ __forceinline__ float to_tf32(float a) {
    uint32_t u;
    asm("cvt.rna.tf32.f32 %0, %1;" : "=r"(u) : "f"(a));
    return __uint_as_float(u);
}

__device__ __forceinline__ void mma_tf32(float c[4],
                                         uint32_t a0, uint32_t a1, uint32_t a2, uint32_t a3,
                                         uint32_t b0, uint32_t b1)
{
    asm volatile(
        "mma.sync.aligned.m16n8k8.row.col.f32.tf32.tf32.f32 "
        "{%0,%1,%2,%3},{%4,%5,%6,%7},{%8,%9},{%0,%1,%2,%3};"
        : "+f"(c[0]), "+f"(c[1]), "+f"(c[2]), "+f"(c[3])
        : "r"(a0), "r"(a1), "r"(a2), "r"(a3), "r"(b0), "r"(b1));
}

// ---------------------------------------------------------------------------
// Kernel 1: h = x @ W^T (TF32 MMA) + fused s_src/s_dst epilogue.
// Block tile 128x64; blockIdx.y selects the output head (64 cols == 1 head),
// so the block holds the COMPLETE head dot-product for its 128 rows.
// ---------------------------------------------------------------------------
#define GBM 128
#define GBN 64
#define GBK 32
#define GPAD 36

__global__ __launch_bounds__(256) void gemm_tf32(const float* __restrict__ x,
                                                 const float* __restrict__ W,
                                                 const float* __restrict__ a_src,
                                                 const float* __restrict__ a_dst)
{
    const int bm = blockIdx.x * GBM;
    const int bo = blockIdx.y * GBN;
    const int head = blockIdx.y;       // GBN == F_ == 64

    __shared__ float As[GBM][GPAD];
    __shared__ float Bs[GBN][GPAD];
    __shared__ float sS[GBM], sD[GBM];

    const int t    = threadIdx.x;
    const int lane = t & 31;
    const int warp = t >> 5;
    const int wm   = warp >> 2;
    const int wn   = warp & 3;

    if (t < GBM) { sS[t] = 0.0f; sD[t] = 0.0f; }

    float acc[4][2][4];
#pragma unroll
    for (int mt = 0; mt < 4; mt++)
#pragma unroll
        for (int nt = 0; nt < 2; nt++)
#pragma unroll
            for (int i = 0; i < 4; i++) acc[mt][nt][i] = 0.0f;

    for (int k0 = 0; k0 < INF_; k0 += GBK) {
        float4 ar[4], br[2];
#pragma unroll
        for (int j = 0; j < 4; j++) {
            int v = t + 256 * j;
            int row = v >> 3;
            int col = (v & 7) * 4;
            ar[j] = *reinterpret_cast<const float4*>(&x[(bm + row) * INF_ + k0 + col]);
        }
#pragma unroll
        for (int j = 0; j < 2; j++) {
            int v = t + 256 * j;
            int row = v >> 3;
            int col = (v & 7) * 4;
            br[j] = *reinterpret_cast<const float4*>(&W[(bo + row) * INF_ + k0 + col]);
        }

        __syncthreads();
#pragma unroll
        for (int j = 0; j < 4; j++) {
            int v = t + 256 * j;
            int row = v >> 3;
            int col = (v & 7) * 4;
            As[row][col + 0] = to_tf32(ar[j].x);
            As[row][col + 1] = to_tf32(ar[j].y);
            As[row][col + 2] = to_tf32(ar[j].z);
            As[row][col + 3] = to_tf32(ar[j].w);
        }
#pragma unroll
        for (int j = 0; j < 2; j++) {
            int v = t + 256 * j;
            int row = v >> 3;
            int col = (v & 7) * 4;
            Bs[row][col + 0] = to_tf32(br[j].x);
            Bs[row][col + 1] = to_tf32(br[j].y);
            Bs[row][col + 2] = to_tf32(br[j].z);
            Bs[row][col + 3] = to_tf32(br[j].w);
        }
        __syncthreads();

#pragma unroll
        for (int ks = 0; ks < 4; ks++) {
            const int kc = ks * 8 + (lane & 3);
            uint32_t Af[4][4];
#pragma unroll
            for (int mt = 0; mt < 4; mt++) {
                const int r0 = wm * 64 + mt * 16 + (lane >> 2);
                Af[mt][0] = __float_as_uint(As[r0][kc]);
                Af[mt][1] = __float_as_uint(As[r0 + 8][kc]);
                Af[mt][2] = __float_as_uint(As[r0][kc + 4]);
                Af[mt][3] = __float_as_uint(As[r0 + 8][kc + 4]);
            }
            uint32_t Bf[2][2];
#pragma unroll
            for (int nt = 0; nt < 2; nt++) {
                const int n0 = wn * 16 + nt * 8 + (lane >> 2);
                Bf[nt][0] = __float_as_uint(Bs[n0][kc]);
                Bf[nt][1] = __float_as_uint(Bs[n0][kc + 4]);
            }
#pragma unroll
            for (int mt = 0; mt < 4; mt++)
#pragma unroll
                for (int nt = 0; nt < 2; nt++)
                    mma_tf32(acc[mt][nt], Af[mt][0], Af[mt][1], Af[mt][2], Af[mt][3],
                             Bf[nt][0], Bf[nt][1]);
        }
    }

    // ---- epilogue A: fp16 h stores
#pragma unroll
    for (int mt = 0; mt < 4; mt++) {
#pragma unroll
        for (int nt = 0; nt < 2; nt++) {
            const int row = bm + wm * 64 + mt * 16 + (lane >> 2);
            const int col = bo + wn * 16 + nt * 8 + (lane & 3) * 2;
            float2 v0 = make_float2(acc[mt][nt][0], acc[mt][nt][1]);
            float2 v1 = make_float2(acc[mt][nt][2], acc[mt][nt][3]);
            *reinterpret_cast<__half2*>(&g_h16[row * HF_ + col]) = __float22half2_rn(v0);
            *reinterpret_cast<__half2*>(&g_h16[(row + 8) * HF_ + col]) = __float22half2_rn(v1);
        }
    }

    // ---- epilogue B: fused s_src/s_dst for this head
    float asv[2][2], adv[2][2];
#pragma unroll
    for (int nt = 0; nt < 2; nt++)
#pragma unroll
        for (int j = 0; j < 2; j++) {
            const int c = wn * 16 + nt * 8 + (lane & 3) * 2 + j;
            asv[nt][j] = a_src[head * F_ + c];
            adv[nt][j] = a_dst[head * F_ + c];
        }

#pragma unroll
    for (int mt = 0; mt < 4; mt++) {
        float ps0 = 0.f, ps1 = 0.f, pd0 = 0.f, pd1 = 0.f;
#pragma unroll
        for (int nt = 0; nt < 2; nt++) {
            ps0 = fmaf(acc[mt][nt][0], asv[nt][0], ps0);
            ps0 = fmaf(acc[mt][nt][1], asv[nt][1], ps0);
            ps1 = fmaf(acc[mt][nt][2], asv[nt][0], ps1);
            ps1 = fmaf(acc[mt][nt][3], asv[nt][1], ps1);
            pd0 = fmaf(acc[mt][nt][0], adv[nt][0], pd0);
            pd0 = fmaf(acc[mt][nt][1], adv[nt][1], pd0);
            pd1 = fmaf(acc[mt][nt][2], adv[nt][0], pd1);
            pd1 = fmaf(acc[mt][nt][3], adv[nt][1], pd1);
        }
        // reduce across the 4 lanes sharing a row
#pragma unroll
        for (int o = 1; o < 4; o <<= 1) {
            ps0 += __shfl_xor_sync(0xFFFFFFFFu, ps0, o);
            ps1 += __shfl_xor_sync(0xFFFFFFFFu, ps1, o);
            pd0 += __shfl_xor_sync(0xFFFFFFFFu, pd0, o);
            pd1 += __shfl_xor_sync(0xFFFFFFFFu, pd1, o);
        }
        if ((lane & 3) == 0) {
            const int r = wm * 64 + mt * 16 + (lane >> 2);
            atomicAdd(&sS[r], ps0);
            atomicAdd(&sS[r + 8], ps1);
            atomicAdd(&sD[r], pd0);
            atomicAdd(&sD[r + 8], pd1);
        }
    }
    __syncthreads();
    if (t < GBM) {
        g_ssrc[(bm + t) * H_ + head] = sS[t];
        g_sdst[(bm + t) * H_ + head] = sD[t];
    }
}

// ---------------------------------------------------------------------------
// Kernel 2: neighbor lists from dense adjacency (DRAM-bound mandatory read)
// ---------------------------------------------------------------------------
__global__ __launch_bounds__(256) void csr_kernel(const float* __restrict__ adj)
{
    const int n = blockIdx.x;
    __shared__ int cnt;
    if (threadIdx.x == 0) cnt = 0;
    __syncthreads();

    const float4* row4 = reinterpret_cast<const float4*>(adj + (long long)n * N_);
    for (int i = threadIdx.x; i < N_ / 4; i += 256) {
        float4 v = row4[i];
        if (v.x != 0.0f) { int p = atomicAdd(&cnt, 1); if (p < MAXD) g_nbrs[n * MAXD + p] = i * 4 + 0; }
        if (v.y != 0.0f) { int p = atomicAdd(&cnt, 1); if (p < MAXD) g_nbrs[n * MAXD + p] = i * 4 + 1; }
        if (v.z != 0.0f) { int p = atomicAdd(&cnt, 1); if (p < MAXD) g_nbrs[n * MAXD + p] = i * 4 + 2; }
        if (v.w != 0.0f) { int p = atomicAdd(&cnt, 1); if (p < MAXD) g_nbrs[n * MAXD + p] = i * 4 + 3; }
    }
    __syncthreads();
    if (threadIdx.x == 0) g_deg[n] = cnt < MAXD ? cnt : MAXD;
}

// ---------------------------------------------------------------------------
// Kernel 3: single-pass sparse softmax + aggregation.
// Warp = one (b,n), all 4 heads; lane owns 16B of the 512B fp16 row.
// p = exp(leaky_relu(s_src+s_dst)) is head-uniform across the lane's 8-lane
// group, so each lane's running sum IS its head's softmax denominator.
// Normalization by 1/sum happens at the store -> no second pass, no p storage.
// ---------------------------------------------------------------------------
#define ATT_NPB 4   // n's per block (8 warps: {b0,b1} x {n0..n3})

__global__ __launch_bounds__(256) void attn_kernel(float* __restrict__ out)
{
    __shared__ int nbS[ATT_NPB][MAXD_S];
    __shared__ int degS[ATT_NPB];

    const int t    = threadIdx.x;
    const int w    = t >> 5;
    const int lane = t & 31;
    const int b    = w & 1;
    const int nsub = w >> 1;
    const int n    = blockIdx.x * ATT_NPB + nsub;
    const int bn   = b * N_ + n;

    if (b == 0) {
        if (lane == 0) degS[nsub] = g_deg[n];
        const int dg = g_deg[n];
        for (int i = lane; i < dg && i < MAXD_S; i += 32)
            nbS[nsub][i] = g_nbrs[n * MAXD + i];
    }
    __syncthreads();

    const int deg  = degS[nsub];
    const int degc = deg < MAXD_S ? deg : MAXD_S;
    const int bN   = b * N_;
    const int head = lane >> 3;

    const float c = g_ssrc[bn * H_ + head];
    const float* __restrict__ sd = g_sdst;
    const uint4* __restrict__ hrow = reinterpret_cast<const uint4*>(g_h16);

    float  sum = 0.0f;
    float2 a0 = make_float2(0.f, 0.f), a1 = a0, a2 = a0, a3 = a0;

    int i = 0;
    for (; i + 2 <= degc; i += 2) {
        const int m0 = nbS[nsub][i];
        const int m1 = nbS[nsub][i + 1];
        float e0 = c + sd[(bN + m0) * H_ + head];
        float e1 = c + sd[(bN + m1) * H_ + head];
        e0 = fmaxf(e0, 0.2f * e0);
        e1 = fmaxf(e1, 0.2f * e1);
        const float p0 = __expf(e0);
        const float p1 = __expf(e1);
        const uint4 v0 = hrow[(bN + m0) * 32 + lane];
        const uint4 v1 = hrow[(bN + m1) * 32 + lane];
        sum += p0 + p1;

        float2 f;
        f = __half22float2(*reinterpret_cast<const __half2*>(&v0.x));
        a0.x = fmaf(p0, f.x, a0.x); a0.y = fmaf(p0, f.y, a0.y);
        f = __half22float2(*reinterpret_cast<const __half2*>(&v0.y));
        a1.x = fmaf(p0, f.x, a1.x); a1.y = fmaf(p0, f.y, a1.y);
        f = __half22float2(*reinterpret_cast<const __half2*>(&v0.z));
        a2.x = fmaf(p0, f.x, a2.x); a2.y = fmaf(p0, f.y, a2.y);
        f = __half22float2(*reinterpret_cast<const __half2*>(&v0.w));
        a3.x = fmaf(p0, f.x, a3.x); a3.y = fmaf(p0, f.y, a3.y);

        f = __half22float2(*reinterpret_cast<const __half2*>(&v1.x));
        a0.x = fmaf(p1, f.x, a0.x); a0.y = fmaf(p1, f.y, a0.y);
        f = __half22float2(*reinterpret_cast<const __half2*>(&v1.y));
        a1.x = fmaf(p1, f.x, a1.x); a1.y = fmaf(p1, f.y, a1.y);
        f = __half22float2(*reinterpret_cast<const __half2*>(&v1.z));
        a2.x = fmaf(p1, f.x, a2.x); a2.y = fmaf(p1, f.y, a2.y);
        f = __half22float2(*reinterpret_cast<const __half2*>(&v1.w));
        a3.x = fmaf(p1, f.x, a3.x); a3.y = fmaf(p1, f.y, a3.y);
    }
    if (i < degc) {
        const int m0 = nbS[nsub][i];
        float e0 = c + sd[(bN + m0) * H_ + head];
        e0 = fmaxf(e0, 0.2f * e0);
        const float p0 = __expf(e0);
        const uint4 v0 = hrow[(bN + m0) * 32 + lane];
        sum += p0;
        float2 f;
        f = __half22float2(*reinterpret_cast<const __half2*>(&v0.x));
        a0.x = fmaf(p0, f.x, a0.x); a0.y = fmaf(p0, f.y, a0.y);
        f = __half22float2(*reinterpret_cast<const __half2*>(&v0.y));
        a1.x = fmaf(p0, f.x, a1.x); a1.y = fmaf(p0, f.y, a1.y);
        f = __half22float2(*reinterpret_cast<const __half2*>(&v0.z));
        a2.x = fmaf(p0, f.x, a2.x); a2.y = fmaf(p0, f.y, a2.y);
        f = __half22float2(*reinterpret_cast<const __half2*>(&v0.w));
        a3.x = fmaf(p0, f.x, a3.x); a3.y = fmaf(p0, f.y, a3.y);
        i++;
    }
    // tail beyond smem capacity (statistically never; correctness guard)
    for (i = degc; i < deg; i++) {
        const int m0 = g_nbrs[n * MAXD + i];
        float e0 = c + sd[(bN + m0) * H_ + head];
        e0 = fmaxf(e0, 0.2f * e0);
        const float p0 = __expf(e0);
        const uint4 v0 = hrow[(bN + m0) * 32 + lane];
        sum += p0;
        float2 f;
        f = __half22float2(*reinterpret_cast<const __half2*>(&v0.x));
        a0.x = fmaf(p0, f.x, a0.x); a0.y = fmaf(p0, f.y, a0.y);
        f = __half22float2(*reinterpret_cast<const __half2*>(&v0.y));
        a1.x = fmaf(p0, f.x, a1.x); a1.y = fmaf(p0, f.y, a1.y);
        f = __half22float2(*reinterpret_cast<const __half2*>(&v0.z));
        a2.x = fmaf(p0, f.x, a2.x); a2.y = fmaf(p0, f.y, a2.y);
        f = __half22float2(*reinterpret_cast<const __half2*>(&v0.w));
        a3.x = fmaf(p0, f.x, a3.x); a3.y = fmaf(p0, f.y, a3.y);
    }

    const float inv = 1.0f / sum;
    float4 o0 = make_float4(a0.x * inv, a0.y * inv, a1.x * inv, a1.y * inv);
    float4 o1 = make_float4(a2.x * inv, a2.y * inv, a3.x * inv, a3.y * inv);
    float4* outp = reinterpret_cast<float4*>(out);
    outp[bn * 64 + lane * 2 + 0] = o0;
    outp[bn * 64 + lane * 2 + 1] = o1;
}

// ---------------------------------------------------------------------------
extern "C" void kernel_launch(void* const* d_in, const int* in_sizes, int n_in,
                              void* d_out, int out_size)
{
    const float* x     = (const float*)d_in[0];
    const float* adj   = (const float*)d_in[1];
    const float* W     = (const float*)d_in[2];
    const float* a_src = (const float*)d_in[3];
    const float* a_dst = (const float*)d_in[4];
    float* out = (float*)d_out;

    gemm_tf32<<<dim3(BN_ / GBM, HF_ / GBN), 256>>>(x, W, a_src, a_dst);
    csr_kernel<<<N_, 256>>>(adj);
    attn_kernel<<<N_ / ATT_NPB, 256>>>(out);
}

// round 5
// speedup vs baseline: 1.5670x; 1.0605x over previous
#include <cuda_runtime.h>
#include <cuda_bf16.h>
#include <cuda_fp16.h>
#include <cstdint>

#define B_   2
#define N_   4096
#define INF_ 256
#define H_   4
#define F_   64
#define BN_  (B_ * N_)      // 8192
#define HF_  (H_ * F_)      // 256
#define MAXD   512
#define MAXD_S 320

#define GEMM_BLOCKS 256     // (BN_/GBM) * (HF_/GBN) = 64*4

// ---------------- scratch (device globals) ----------------------------------
__device__ __align__(16) __half g_h16[BN_ * HF_];
__device__ __align__(16) float  g_ssrc[BN_ * H_];
__device__ __align__(16) float  g_sdst[BN_ * H_];
__device__ int g_nbrs[N_ * MAXD];
__device__ int g_deg[N_];

// ---------------------------------------------------------------------------
__device__ __forceinline__ float to_tf32(float a) {
    uint32_t u;
    asm("cvt.rna.tf32.f32 %0, %1;" : "=r"(u) : "f"(a));
    return __uint_as_float(u);
}

__device__ __forceinline__ void mma_tf32(float c[4],
                                         uint32_t a0, uint32_t a1, uint32_t a2, uint32_t a3,
                                         uint32_t b0, uint32_t b1)
{
    asm volatile(
        "mma.sync.aligned.m16n8k8.row.col.f32.tf32.tf32.f32 "
        "{%0,%1,%2,%3},{%4,%5,%6,%7},{%8,%9},{%0,%1,%2,%3};"
        : "+f"(c[0]), "+f"(c[1]), "+f"(c[2]), "+f"(c[3])
        : "r"(a0), "r"(a1), "r"(a2), "r"(a3), "r"(b0), "r"(b1));
}

// ---------------------------------------------------------------------------
// Kernel 1 (fused): blocks [0,256) do the TF32 GEMM + s epilogue (tensor/
// latency bound); blocks [256, 256+4096) scan the adjacency into neighbor
// lists (DRAM bound). Disjoint pipes -> near-full overlap in one wave set.
// GEMM: 128x64 tile, BK=32, DOUBLE-BUFFERED smem, 1 syncthreads per K-iter.
// ---------------------------------------------------------------------------
#define GBM 128
#define GBN 64
#define GBK 32
#define GPAD 36
#define KITERS (INF_ / GBK)   // 8

__global__ __launch_bounds__(256) void fused_gemm_csr(const float* __restrict__ x,
                                                      const float* __restrict__ W,
                                                      const float* __restrict__ a_src,
                                                      const float* __restrict__ a_dst,
                                                      const float* __restrict__ adj)
{
    __shared__ float As[2][GBM][GPAD];
    __shared__ float Bs[2][GBN][GPAD];
    __shared__ float sS[GBM], sD[GBM];
    __shared__ int cnt;

    const int bid = blockIdx.x;
    const int t   = threadIdx.x;

    // ================= CSR path =================
    if (bid >= GEMM_BLOCKS) {
        const int n = bid - GEMM_BLOCKS;
        if (t == 0) cnt = 0;
        __syncthreads();
        const float4* row4 = reinterpret_cast<const float4*>(adj + (long long)n * N_);
#pragma unroll 4
        for (int i = t; i < N_ / 4; i += 256) {
            float4 v = row4[i];
            if (v.x != 0.0f) { int p = atomicAdd(&cnt, 1); if (p < MAXD) g_nbrs[n * MAXD + p] = i * 4 + 0; }
            if (v.y != 0.0f) { int p = atomicAdd(&cnt, 1); if (p < MAXD) g_nbrs[n * MAXD + p] = i * 4 + 1; }
            if (v.z != 0.0f) { int p = atomicAdd(&cnt, 1); if (p < MAXD) g_nbrs[n * MAXD + p] = i * 4 + 2; }
            if (v.w != 0.0f) { int p = atomicAdd(&cnt, 1); if (p < MAXD) g_nbrs[n * MAXD + p] = i * 4 + 3; }
        }
        __syncthreads();
        if (t == 0) g_deg[n] = cnt < MAXD ? cnt : MAXD;
        return;
    }

    // ================= GEMM path =================
    const int head = bid & 3;
    const int bm   = (bid >> 2) * GBM;
    const int bo   = head * GBN;

    const int lane = t & 31;
    const int warp = t >> 5;
    const int wm   = warp >> 2;
    const int wn   = warp & 3;

    if (t < GBM) { sS[t] = 0.0f; sD[t] = 0.0f; }

    float acc[4][2][4];
#pragma unroll
    for (int mt = 0; mt < 4; mt++)
#pragma unroll
        for (int nt = 0; nt < 2; nt++)
#pragma unroll
            for (int i = 0; i < 4; i++) acc[mt][nt][i] = 0.0f;

    // addressing for the staged loads
    const int arow = t >> 3;            // A/B row for this thread's float4s
    const int acol = (t & 7) * 4;       // col offset within BK

    float4 ar[4], br[2];

    // prologue: stage tile 0
#pragma unroll
    for (int j = 0; j < 4; j++)
        ar[j] = *reinterpret_cast<const float4*>(&x[(bm + arow + 32 * j) * INF_ + acol]);
#pragma unroll
    for (int j = 0; j < 2; j++)
        br[j] = *reinterpret_cast<const float4*>(&W[(bo + arow + 32 * j) * INF_ + acol]);
#pragma unroll
    for (int j = 0; j < 4; j++) {
        const int r = arow + 32 * j;
        As[0][r][acol + 0] = to_tf32(ar[j].x);
        As[0][r][acol + 1] = to_tf32(ar[j].y);
        As[0][r][acol + 2] = to_tf32(ar[j].z);
        As[0][r][acol + 3] = to_tf32(ar[j].w);
    }
#pragma unroll
    for (int j = 0; j < 2; j++) {
        const int r = arow + 32 * j;
        Bs[0][r][acol + 0] = to_tf32(br[j].x);
        Bs[0][r][acol + 1] = to_tf32(br[j].y);
        Bs[0][r][acol + 2] = to_tf32(br[j].z);
        Bs[0][r][acol + 3] = to_tf32(br[j].w);
    }
    __syncthreads();

#pragma unroll
    for (int kt = 0; kt < KITERS; kt++) {
        const int cur = kt & 1;
        const int nxt = cur ^ 1;

        // issue next tile's global loads before compute (latency hiding)
        if (kt + 1 < KITERS) {
            const int k0 = (kt + 1) * GBK;
#pragma unroll
            for (int j = 0; j < 4; j++)
                ar[j] = *reinterpret_cast<const float4*>(&x[(bm + arow + 32 * j) * INF_ + k0 + acol]);
#pragma unroll
            for (int j = 0; j < 2; j++)
                br[j] = *reinterpret_cast<const float4*>(&W[(bo + arow + 32 * j) * INF_ + k0 + acol]);
        }

        // compute on current buffer
#pragma unroll
        for (int ks = 0; ks < 4; ks++) {
            const int kc = ks * 8 + (lane & 3);
            uint32_t Af[4][4];
#pragma unroll
            for (int mt = 0; mt < 4; mt++) {
                const int r0 = wm * 64 + mt * 16 + (lane >> 2);
                Af[mt][0] = __float_as_uint(As[cur][r0][kc]);
                Af[mt][1] = __float_as_uint(As[cur][r0 + 8][kc]);
                Af[mt][2] = __float_as_uint(As[cur][r0][kc + 4]);
                Af[mt][3] = __float_as_uint(As[cur][r0 + 8][kc + 4]);
            }
            uint32_t Bf[2][2];
#pragma unroll
            for (int nt = 0; nt < 2; nt++) {
                const int n0 = wn * 16 + nt * 8 + (lane >> 2);
                Bf[nt][0] = __float_as_uint(Bs[cur][n0][kc]);
                Bf[nt][1] = __float_as_uint(Bs[cur][n0][kc + 4]);
            }
#pragma unroll
            for (int mt = 0; mt < 4; mt++)
#pragma unroll
                for (int nt = 0; nt < 2; nt++)
                    mma_tf32(acc[mt][nt], Af[mt][0], Af[mt][1], Af[mt][2], Af[mt][3],
                             Bf[nt][0], Bf[nt][1]);
        }

        // stage next tile into the other buffer; single sync per iter
        if (kt + 1 < KITERS) {
#pragma unroll
            for (int j = 0; j < 4; j++) {
                const int r = arow + 32 * j;
                As[nxt][r][acol + 0] = to_tf32(ar[j].x);
                As[nxt][r][acol + 1] = to_tf32(ar[j].y);
                As[nxt][r][acol + 2] = to_tf32(ar[j].z);
                As[nxt][r][acol + 3] = to_tf32(ar[j].w);
            }
#pragma unroll
            for (int j = 0; j < 2; j++) {
                const int r = arow + 32 * j;
                Bs[nxt][r][acol + 0] = to_tf32(br[j].x);
                Bs[nxt][r][acol + 1] = to_tf32(br[j].y);
                Bs[nxt][r][acol + 2] = to_tf32(br[j].z);
                Bs[nxt][r][acol + 3] = to_tf32(br[j].w);
            }
            __syncthreads();
        }
    }

    // ---- epilogue A: fp16 h stores
#pragma unroll
    for (int mt = 0; mt < 4; mt++) {
#pragma unroll
        for (int nt = 0; nt < 2; nt++) {
            const int row = bm + wm * 64 + mt * 16 + (lane >> 2);
            const int col = bo + wn * 16 + nt * 8 + (lane & 3) * 2;
            float2 v0 = make_float2(acc[mt][nt][0], acc[mt][nt][1]);
            float2 v1 = make_float2(acc[mt][nt][2], acc[mt][nt][3]);
            *reinterpret_cast<__half2*>(&g_h16[row * HF_ + col]) = __float22half2_rn(v0);
            *reinterpret_cast<__half2*>(&g_h16[(row + 8) * HF_ + col]) = __float22half2_rn(v1);
        }
    }

    // ---- epilogue B: fused s_src/s_dst for this head
    float asv[2][2], adv[2][2];
#pragma unroll
    for (int nt = 0; nt < 2; nt++)
#pragma unroll
        for (int j = 0; j < 2; j++) {
            const int c = wn * 16 + nt * 8 + (lane & 3) * 2 + j;
            asv[nt][j] = a_src[head * F_ + c];
            adv[nt][j] = a_dst[head * F_ + c];
        }

    __syncthreads();   // sS/sD zeroed (prologue) and all prior smem traffic done
#pragma unroll
    for (int mt = 0; mt < 4; mt++) {
        float ps0 = 0.f, ps1 = 0.f, pd0 = 0.f, pd1 = 0.f;
#pragma unroll
        for (int nt = 0; nt < 2; nt++) {
            ps0 = fmaf(acc[mt][nt][0], asv[nt][0], ps0);
            ps0 = fmaf(acc[mt][nt][1], asv[nt][1], ps0);
            ps1 = fmaf(acc[mt][nt][2], asv[nt][0], ps1);
            ps1 = fmaf(acc[mt][nt][3], asv[nt][1], ps1);
            pd0 = fmaf(acc[mt][nt][0], adv[nt][0], pd0);
            pd0 = fmaf(acc[mt][nt][1], adv[nt][1], pd0);
            pd1 = fmaf(acc[mt][nt][2], adv[nt][0], pd1);
            pd1 = fmaf(acc[mt][nt][3], adv[nt][1], pd1);
        }
#pragma unroll
        for (int o = 1; o < 4; o <<= 1) {
            ps0 += __shfl_xor_sync(0xFFFFFFFFu, ps0, o);
            ps1 += __shfl_xor_sync(0xFFFFFFFFu, ps1, o);
            pd0 += __shfl_xor_sync(0xFFFFFFFFu, pd0, o);
            pd1 += __shfl_xor_sync(0xFFFFFFFFu, pd1, o);
        }
        if ((lane & 3) == 0) {
            const int r = wm * 64 + mt * 16 + (lane >> 2);
            atomicAdd(&sS[r], ps0);
            atomicAdd(&sS[r + 8], ps1);
            atomicAdd(&sD[r], pd0);
            atomicAdd(&sD[r + 8], pd1);
        }
    }
    __syncthreads();
    if (t < GBM) {
        g_ssrc[(bm + t) * H_ + head] = sS[t];
        g_sdst[(bm + t) * H_ + head] = sD[t];
    }
}

// ---------------------------------------------------------------------------
// Kernel 2: single-pass sparse softmax + aggregation (unchanged from R4).
// ---------------------------------------------------------------------------
#define ATT_NPB 4

__global__ __launch_bounds__(256) void attn_kernel(float* __restrict__ out)
{
    __shared__ int nbS[ATT_NPB][MAXD_S];
    __shared__ int degS[ATT_NPB];

    const int t    = threadIdx.x;
    const int w    = t >> 5;
    const int lane = t & 31;
    const int b    = w & 1;
    const int nsub = w >> 1;
    const int n    = blockIdx.x * ATT_NPB + nsub;
    const int bn   = b * N_ + n;

    if (b == 0) {
        if (lane == 0) degS[nsub] = g_deg[n];
        const int dg = g_deg[n];
        for (int i = lane; i < dg && i < MAXD_S; i += 32)
            nbS[nsub][i] = g_nbrs[n * MAXD + i];
    }
    __syncthreads();

    const int deg  = degS[nsub];
    const int degc = deg < MAXD_S ? deg : MAXD_S;
    const int bN   = b * N_;
    const int head = lane >> 3;

    const float c = g_ssrc[bn * H_ + head];
    const float* __restrict__ sd = g_sdst;
    const uint4* __restrict__ hrow = reinterpret_cast<const uint4*>(g_h16);

    float  sum = 0.0f;
    float2 a0 = make_float2(0.f, 0.f), a1 = a0, a2 = a0, a3 = a0;

    int i = 0;
    for (; i + 2 <= degc; i += 2) {
        const int m0 = nbS[nsub][i];
        const int m1 = nbS[nsub][i + 1];
        float e0 = c + sd[(bN + m0) * H_ + head];
        float e1 = c + sd[(bN + m1) * H_ + head];
        e0 = fmaxf(e0, 0.2f * e0);
        e1 = fmaxf(e1, 0.2f * e1);
        const float p0 = __expf(e0);
        const float p1 = __expf(e1);
        const uint4 v0 = hrow[(bN + m0) * 32 + lane];
        const uint4 v1 = hrow[(bN + m1) * 32 + lane];
        sum += p0 + p1;

        float2 f;
        f = __half22float2(*reinterpret_cast<const __half2*>(&v0.x));
        a0.x = fmaf(p0, f.x, a0.x); a0.y = fmaf(p0, f.y, a0.y);
        f = __half22float2(*reinterpret_cast<const __half2*>(&v0.y));
        a1.x = fmaf(p0, f.x, a1.x); a1.y = fmaf(p0, f.y, a1.y);
        f = __half22float2(*reinterpret_cast<const __half2*>(&v0.z));
        a2.x = fmaf(p0, f.x, a2.x); a2.y = fmaf(p0, f.y, a2.y);
        f = __half22float2(*reinterpret_cast<const __half2*>(&v0.w));
        a3.x = fmaf(p0, f.x, a3.x); a3.y = fmaf(p0, f.y, a3.y);

        f = __half22float2(*reinterpret_cast<const __half2*>(&v1.x));
        a0.x = fmaf(p1, f.x, a0.x); a0.y = fmaf(p1, f.y, a0.y);
        f = __half22float2(*reinterpret_cast<const __half2*>(&v1.y));
        a1.x = fmaf(p1, f.x, a1.x); a1.y = fmaf(p1, f.y, a1.y);
        f = __half22float2(*reinterpret_cast<const __half2*>(&v1.z));
        a2.x = fmaf(p1, f.x, a2.x); a2.y = fmaf(p1, f.y, a2.y);
        f = __half22float2(*reinterpret_cast<const __half2*>(&v1.w));
        a3.x = fmaf(p1, f.x, a3.x); a3.y = fmaf(p1, f.y, a3.y);
    }
    if (i < degc) {
        const int m0 = nbS[nsub][i];
        float e0 = c + sd[(bN + m0) * H_ + head];
        e0 = fmaxf(e0, 0.2f * e0);
        const float p0 = __expf(e0);
        const uint4 v0 = hrow[(bN + m0) * 32 + lane];
        sum += p0;
        float2 f;
        f = __half22float2(*reinterpret_cast<const __half2*>(&v0.x));
        a0.x = fmaf(p0, f.x, a0.x); a0.y = fmaf(p0, f.y, a0.y);
        f = __half22float2(*reinterpret_cast<const __half2*>(&v0.y));
        a1.x = fmaf(p0, f.x, a1.x); a1.y = fmaf(p0, f.y, a1.y);
        f = __half22float2(*reinterpret_cast<const __half2*>(&v0.z));
        a2.x = fmaf(p0, f.x, a2.x); a2.y = fmaf(p0, f.y, a2.y);
        f = __half22float2(*reinterpret_cast<const __half2*>(&v0.w));
        a3.x = fmaf(p0, f.x, a3.x); a3.y = fmaf(p0, f.y, a3.y);
        i++;
    }
    for (i = degc; i < deg; i++) {
        const int m0 = g_nbrs[n * MAXD + i];
        float e0 = c + sd[(bN + m0) * H_ + head];
        e0 = fmaxf(e0, 0.2f * e0);
        const float p0 = __expf(e0);
        const uint4 v0 = hrow[(bN + m0) * 32 + lane];
        sum += p0;
        float2 f;
        f = __half22float2(*reinterpret_cast<const __half2*>(&v0.x));
        a0.x = fmaf(p0, f.x, a0.x); a0.y = fmaf(p0, f.y, a0.y);
        f = __half22float2(*reinterpret_cast<const __half2*>(&v0.y));
        a1.x = fmaf(p0, f.x, a1.x); a1.y = fmaf(p0, f.y, a1.y);
        f = __half22float2(*reinterpret_cast<const __half2*>(&v0.z));
        a2.x = fmaf(p0, f.x, a2.x); a2.y = fmaf(p0, f.y, a2.y);
        f = __half22float2(*reinterpret_cast<const __half2*>(&v0.w));
        a3.x = fmaf(p0, f.x, a3.x); a3.y = fmaf(p0, f.y, a3.y);
    }

    const float inv = 1.0f / sum;
    float4 o0 = make_float4(a0.x * inv, a0.y * inv, a1.x * inv, a1.y * inv);
    float4 o1 = make_float4(a2.x * inv, a2.y * inv, a3.x * inv, a3.y * inv);
    float4* outp = reinterpret_cast<float4*>(out);
    outp[bn * 64 + lane * 2 + 0] = o0;
    outp[bn * 64 + lane * 2 + 1] = o1;
}

// ---------------------------------------------------------------------------
extern "C" void kernel_launch(void* const* d_in, const int* in_sizes, int n_in,
                              void* d_out, int out_size)
{
    const float* x     = (const float*)d_in[0];
    const float* adj   = (const float*)d_in[1];
    const float* W     = (const float*)d_in[2];
    const float* a_src = (const float*)d_in[3];
    const float* a_dst = (const float*)d_in[4];
    float* out = (float*)d_out;

    fused_gemm_csr<<<GEMM_BLOCKS + N_, 256>>>(x, W, a_src, a_dst, adj);
    attn_kernel<<<N_ / ATT_NPB, 256>>>(out);
}

// round 6
// speedup vs baseline: 1.6012x; 1.0218x over previous
#include <cuda_runtime.h>
#include <cuda_bf16.h>
#include <cuda_fp16.h>
#include <cstdint>

#define B_   2
#define N_   4096
#define INF_ 256
#define H_   4
#define F_   64
#define BN_  (B_ * N_)      // 8192
#define HF_  (H_ * F_)      // 256
#define MAXD   512
#define MAXD_S 160          // smem capacity (deg mean ~82, max ~125; tail fallback beyond)

#define GEMM_BLOCKS 256     // (BN_/GBM) * (HF_/GBN) = 64*4

// ---------------- scratch (device globals) ----------------------------------
__device__ __align__(16) __half g_h16[BN_ * HF_];
__device__ __align__(16) float  g_ssrc[BN_ * H_];
__device__ __align__(16) float  g_sdst[BN_ * H_];
__device__ int g_nbrs[N_ * MAXD];
__device__ int g_deg[N_];

// ---------------------------------------------------------------------------
__device__ __forceinline__ float to_tf32(float a) {
    uint32_t u;
    asm("cvt.rna.tf32.f32 %0, %1;" : "=r"(u) : "f"(a));
    return __uint_as_float(u);
}

__device__ __forceinline__ void mma_tf32(float c[4],
                                         uint32_t a0, uint32_t a1, uint32_t a2, uint32_t a3,
                                         uint32_t b0, uint32_t b1)
{
    asm volatile(
        "mma.sync.aligned.m16n8k8.row.col.f32.tf32.tf32.f32 "
        "{%0,%1,%2,%3},{%4,%5,%6,%7},{%8,%9},{%0,%1,%2,%3};"
        : "+f"(c[0]), "+f"(c[1]), "+f"(c[2]), "+f"(c[3])
        : "r"(a0), "r"(a1), "r"(a2), "r"(a3), "r"(b0), "r"(b1));
}

// ---------------------------------------------------------------------------
// Kernel 1 (fused): blocks [0,256) = TF32 GEMM + s epilogue; blocks
// [256,256+4096) = adjacency scan. Unchanged from R5.
// ---------------------------------------------------------------------------
#define GBM 128
#define GBN 64
#define GBK 32
#define GPAD 36
#define KITERS (INF_ / GBK)   // 8

__global__ __launch_bounds__(256) void fused_gemm_csr(const float* __restrict__ x,
                                                      const float* __restrict__ W,
                                                      const float* __restrict__ a_src,
                                                      const float* __restrict__ a_dst,
                                                      const float* __restrict__ adj)
{
    __shared__ float As[2][GBM][GPAD];
    __shared__ float Bs[2][GBN][GPAD];
    __shared__ float sS[GBM], sD[GBM];
    __shared__ int cnt;

    const int bid = blockIdx.x;
    const int t   = threadIdx.x;

    // ================= CSR path =================
    if (bid >= GEMM_BLOCKS) {
        const int n = bid - GEMM_BLOCKS;
        if (t == 0) cnt = 0;
        __syncthreads();
        const float4* row4 = reinterpret_cast<const float4*>(adj + (long long)n * N_);
#pragma unroll 4
        for (int i = t; i < N_ / 4; i += 256) {
            float4 v = row4[i];
            if (v.x != 0.0f) { int p = atomicAdd(&cnt, 1); if (p < MAXD) g_nbrs[n * MAXD + p] = i * 4 + 0; }
            if (v.y != 0.0f) { int p = atomicAdd(&cnt, 1); if (p < MAXD) g_nbrs[n * MAXD + p] = i * 4 + 1; }
            if (v.z != 0.0f) { int p = atomicAdd(&cnt, 1); if (p < MAXD) g_nbrs[n * MAXD + p] = i * 4 + 2; }
            if (v.w != 0.0f) { int p = atomicAdd(&cnt, 1); if (p < MAXD) g_nbrs[n * MAXD + p] = i * 4 + 3; }
        }
        __syncthreads();
        if (t == 0) g_deg[n] = cnt < MAXD ? cnt : MAXD;
        return;
    }

    // ================= GEMM path =================
    const int head = bid & 3;
    const int bm   = (bid >> 2) * GBM;
    const int bo   = head * GBN;

    const int lane = t & 31;
    const int warp = t >> 5;
    const int wm   = warp >> 2;
    const int wn   = warp & 3;

    if (t < GBM) { sS[t] = 0.0f; sD[t] = 0.0f; }

    float acc[4][2][4];
#pragma unroll
    for (int mt = 0; mt < 4; mt++)
#pragma unroll
        for (int nt = 0; nt < 2; nt++)
#pragma unroll
            for (int i = 0; i < 4; i++) acc[mt][nt][i] = 0.0f;

    const int arow = t >> 3;
    const int acol = (t & 7) * 4;

    float4 ar[4], br[2];

#pragma unroll
    for (int j = 0; j < 4; j++)
        ar[j] = *reinterpret_cast<const float4*>(&x[(bm + arow + 32 * j) * INF_ + acol]);
#pragma unroll
    for (int j = 0; j < 2; j++)
        br[j] = *reinterpret_cast<const float4*>(&W[(bo + arow + 32 * j) * INF_ + acol]);
#pragma unroll
    for (int j = 0; j < 4; j++) {
        const int r = arow + 32 * j;
        As[0][r][acol + 0] = to_tf32(ar[j].x);
        As[0][r][acol + 1] = to_tf32(ar[j].y);
        As[0][r][acol + 2] = to_tf32(ar[j].z);
        As[0][r][acol + 3] = to_tf32(ar[j].w);
    }
#pragma unroll
    for (int j = 0; j < 2; j++) {
        const int r = arow + 32 * j;
        Bs[0][r][acol + 0] = to_tf32(br[j].x);
        Bs[0][r][acol + 1] = to_tf32(br[j].y);
        Bs[0][r][acol + 2] = to_tf32(br[j].z);
        Bs[0][r][acol + 3] = to_tf32(br[j].w);
    }
    __syncthreads();

#pragma unroll
    for (int kt = 0; kt < KITERS; kt++) {
        const int cur = kt & 1;
        const int nxt = cur ^ 1;

        if (kt + 1 < KITERS) {
            const int k0 = (kt + 1) * GBK;
#pragma unroll
            for (int j = 0; j < 4; j++)
                ar[j] = *reinterpret_cast<const float4*>(&x[(bm + arow + 32 * j) * INF_ + k0 + acol]);
#pragma unroll
            for (int j = 0; j < 2; j++)
                br[j] = *reinterpret_cast<const float4*>(&W[(bo + arow + 32 * j) * INF_ + k0 + acol]);
        }

#pragma unroll
        for (int ks = 0; ks < 4; ks++) {
            const int kc = ks * 8 + (lane & 3);
            uint32_t Af[4][4];
#pragma unroll
            for (int mt = 0; mt < 4; mt++) {
                const int r0 = wm * 64 + mt * 16 + (lane >> 2);
                Af[mt][0] = __float_as_uint(As[cur][r0][kc]);
                Af[mt][1] = __float_as_uint(As[cur][r0 + 8][kc]);
                Af[mt][2] = __float_as_uint(As[cur][r0][kc + 4]);
                Af[mt][3] = __float_as_uint(As[cur][r0 + 8][kc + 4]);
            }
            uint32_t Bf[2][2];
#pragma unroll
            for (int nt = 0; nt < 2; nt++) {
                const int n0 = wn * 16 + nt * 8 + (lane >> 2);
                Bf[nt][0] = __float_as_uint(Bs[cur][n0][kc]);
                Bf[nt][1] = __float_as_uint(Bs[cur][n0][kc + 4]);
            }
#pragma unroll
            for (int mt = 0; mt < 4; mt++)
#pragma unroll
                for (int nt = 0; nt < 2; nt++)
                    mma_tf32(acc[mt][nt], Af[mt][0], Af[mt][1], Af[mt][2], Af[mt][3],
                             Bf[nt][0], Bf[nt][1]);
        }

        if (kt + 1 < KITERS) {
#pragma unroll
            for (int j = 0; j < 4; j++) {
                const int r = arow + 32 * j;
                As[nxt][r][acol + 0] = to_tf32(ar[j].x);
                As[nxt][r][acol + 1] = to_tf32(ar[j].y);
                As[nxt][r][acol + 2] = to_tf32(ar[j].z);
                As[nxt][r][acol + 3] = to_tf32(ar[j].w);
            }
#pragma unroll
            for (int j = 0; j < 2; j++) {
                const int r = arow + 32 * j;
                Bs[nxt][r][acol + 0] = to_tf32(br[j].x);
                Bs[nxt][r][acol + 1] = to_tf32(br[j].y);
                Bs[nxt][r][acol + 2] = to_tf32(br[j].z);
                Bs[nxt][r][acol + 3] = to_tf32(br[j].w);
            }
            __syncthreads();
        }
    }

#pragma unroll
    for (int mt = 0; mt < 4; mt++) {
#pragma unroll
        for (int nt = 0; nt < 2; nt++) {
            const int row = bm + wm * 64 + mt * 16 + (lane >> 2);
            const int col = bo + wn * 16 + nt * 8 + (lane & 3) * 2;
            float2 v0 = make_float2(acc[mt][nt][0], acc[mt][nt][1]);
            float2 v1 = make_float2(acc[mt][nt][2], acc[mt][nt][3]);
            *reinterpret_cast<__half2*>(&g_h16[row * HF_ + col]) = __float22half2_rn(v0);
            *reinterpret_cast<__half2*>(&g_h16[(row + 8) * HF_ + col]) = __float22half2_rn(v1);
        }
    }

    float asv[2][2], adv[2][2];
#pragma unroll
    for (int nt = 0; nt < 2; nt++)
#pragma unroll
        for (int j = 0; j < 2; j++) {
            const int c = wn * 16 + nt * 8 + (lane & 3) * 2 + j;
            asv[nt][j] = a_src[head * F_ + c];
            adv[nt][j] = a_dst[head * F_ + c];
        }

    __syncthreads();
#pragma unroll
    for (int mt = 0; mt < 4; mt++) {
        float ps0 = 0.f, ps1 = 0.f, pd0 = 0.f, pd1 = 0.f;
#pragma unroll
        for (int nt = 0; nt < 2; nt++) {
            ps0 = fmaf(acc[mt][nt][0], asv[nt][0], ps0);
            ps0 = fmaf(acc[mt][nt][1], asv[nt][1], ps0);
            ps1 = fmaf(acc[mt][nt][2], asv[nt][0], ps1);
            ps1 = fmaf(acc[mt][nt][3], asv[nt][1], ps1);
            pd0 = fmaf(acc[mt][nt][0], adv[nt][0], pd0);
            pd0 = fmaf(acc[mt][nt][1], adv[nt][1], pd0);
            pd1 = fmaf(acc[mt][nt][2], adv[nt][0], pd1);
            pd1 = fmaf(acc[mt][nt][3], adv[nt][1], pd1);
        }
#pragma unroll
        for (int o = 1; o < 4; o <<= 1) {
            ps0 += __shfl_xor_sync(0xFFFFFFFFu, ps0, o);
            ps1 += __shfl_xor_sync(0xFFFFFFFFu, ps1, o);
            pd0 += __shfl_xor_sync(0xFFFFFFFFu, pd0, o);
            pd1 += __shfl_xor_sync(0xFFFFFFFFu, pd1, o);
        }
        if ((lane & 3) == 0) {
            const int r = wm * 64 + mt * 16 + (lane >> 2);
            atomicAdd(&sS[r], ps0);
            atomicAdd(&sS[r + 8], ps1);
            atomicAdd(&sD[r], pd0);
            atomicAdd(&sD[r + 8], pd1);
        }
    }
    __syncthreads();
    if (t < GBM) {
        g_ssrc[(bm + t) * H_ + head] = sS[t];
        g_sdst[(bm + t) * H_ + head] = sD[t];
    }
}

// ---------------------------------------------------------------------------
// Kernel 2 (attn v4): warp = one (b,n), all 4 heads.
// Phase 1 STRIDED: lane i handles neighbors i, i+32, ...: one float4 s_dst
// load -> 4 exps -> head-major smem p + running sum4. (exp cost /32 vs R5.)
// Phase 2: tight gather; per neighbor-pair one LDS.64 p, one LDS.64 nb,
// two LDG.128, 16 cvt+FFMA. Normalize at store.
// ---------------------------------------------------------------------------
#define ATT_NPB 4   // n's per block; 8 warps = {b0,b1} x {n0..n3}

__global__ __launch_bounds__(256) void attn_kernel(float* __restrict__ out)
{
    __shared__ int   nbS[ATT_NPB][MAXD_S];
    __shared__ float pS[8][H_ * MAXD_S];    // head-major p per warp
    __shared__ int   degS[ATT_NPB];

    const int t    = threadIdx.x;
    const int w    = t >> 5;
    const int lane = t & 31;
    const int b    = w & 1;
    const int nsub = w >> 1;
    const int n    = blockIdx.x * ATT_NPB + nsub;
    const int bn   = b * N_ + n;

    if (b == 0) {
        if (lane == 0) degS[nsub] = g_deg[n];
        const int dg = g_deg[n];
        for (int i = lane; i < dg && i < MAXD_S; i += 32)
            nbS[nsub][i] = g_nbrs[n * MAXD + i];
    }
    __syncthreads();

    const int deg  = degS[nsub];
    const int degc = deg < MAXD_S ? deg : MAXD_S;
    const int bN   = b * N_;

    const float4 c4 = *reinterpret_cast<const float4*>(&g_ssrc[bn * H_]);
    const float4* __restrict__ sd4 = reinterpret_cast<const float4*>(g_sdst);

    // ---- phase 1: strided p computation (all heads), head-major smem
    float4 sum4 = make_float4(0.f, 0.f, 0.f, 0.f);
    for (int i = lane; i < degc; i += 32) {
        const int m = nbS[nsub][i];
        float4 sdv = sd4[bN + m];
        float ex = c4.x + sdv.x, ey = c4.y + sdv.y, ez = c4.z + sdv.z, ew = c4.w + sdv.w;
        ex = fmaxf(ex, 0.2f * ex);
        ey = fmaxf(ey, 0.2f * ey);
        ez = fmaxf(ez, 0.2f * ez);
        ew = fmaxf(ew, 0.2f * ew);
        float px = __expf(ex), py = __expf(ey), pz = __expf(ez), pw = __expf(ew);
        pS[w][0 * MAXD_S + i] = px;
        pS[w][1 * MAXD_S + i] = py;
        pS[w][2 * MAXD_S + i] = pz;
        pS[w][3 * MAXD_S + i] = pw;
        sum4.x += px; sum4.y += py; sum4.z += pz; sum4.w += pw;
    }
    // tail beyond smem capacity: sum only (p recomputed in phase 2 tail)
    for (int i = degc + lane; i < deg; i += 32) {
        const int m = g_nbrs[n * MAXD + i];
        float4 sdv = sd4[bN + m];
        float ex = c4.x + sdv.x, ey = c4.y + sdv.y, ez = c4.z + sdv.z, ew = c4.w + sdv.w;
        ex = fmaxf(ex, 0.2f * ex);
        ey = fmaxf(ey, 0.2f * ey);
        ez = fmaxf(ez, 0.2f * ez);
        ew = fmaxf(ew, 0.2f * ew);
        sum4.x += __expf(ex); sum4.y += __expf(ey); sum4.z += __expf(ez); sum4.w += __expf(ew);
    }
#pragma unroll
    for (int o = 16; o > 0; o >>= 1) {
        sum4.x += __shfl_xor_sync(0xFFFFFFFFu, sum4.x, o);
        sum4.y += __shfl_xor_sync(0xFFFFFFFFu, sum4.y, o);
        sum4.z += __shfl_xor_sync(0xFFFFFFFFu, sum4.z, o);
        sum4.w += __shfl_xor_sync(0xFFFFFFFFu, sum4.w, o);
    }

    const int head = lane >> 3;
    float invh = (head & 2) ? ((head & 1) ? sum4.w : sum4.z)
                            : ((head & 1) ? sum4.y : sum4.x);
    invh = 1.0f / invh;

    __syncwarp();

    // ---- phase 2: gather + weighted accumulate
    const uint4* __restrict__ hrow = reinterpret_cast<const uint4*>(g_h16) + (long long)bN * 32 + lane;
    const float* __restrict__ pw = &pS[w][head * MAXD_S];
    const int*   __restrict__ nbp = &nbS[nsub][0];

    float2 a0 = make_float2(0.f, 0.f), a1 = a0, a2 = a0, a3 = a0;

    int i = 0;
    for (; i + 2 <= degc; i += 2) {
        const int2   mm = *reinterpret_cast<const int2*>(&nbp[i]);    // 8B aligned
        const float2 pp = *reinterpret_cast<const float2*>(&pw[i]);   // 8B aligned
        const uint4 v0 = hrow[mm.x * 32];
        const uint4 v1 = hrow[mm.y * 32];

        float2 f;
        f = __half22float2(*reinterpret_cast<const __half2*>(&v0.x));
        a0.x = fmaf(pp.x, f.x, a0.x); a0.y = fmaf(pp.x, f.y, a0.y);
        f = __half22float2(*reinterpret_cast<const __half2*>(&v0.y));
        a1.x = fmaf(pp.x, f.x, a1.x); a1.y = fmaf(pp.x, f.y, a1.y);
        f = __half22float2(*reinterpret_cast<const __half2*>(&v0.z));
        a2.x = fmaf(pp.x, f.x, a2.x); a2.y = fmaf(pp.x, f.y, a2.y);
        f = __half22float2(*reinterpret_cast<const __half2*>(&v0.w));
        a3.x = fmaf(pp.x, f.x, a3.x); a3.y = fmaf(pp.x, f.y, a3.y);

        f = __half22float2(*reinterpret_cast<const __half2*>(&v1.x));
        a0.x = fmaf(pp.y, f.x, a0.x); a0.y = fmaf(pp.y, f.y, a0.y);
        f = __half22float2(*reinterpret_cast<const __half2*>(&v1.y));
        a1.x = fmaf(pp.y, f.x, a1.x); a1.y = fmaf(pp.y, f.y, a1.y);
        f = __half22float2(*reinterpret_cast<const __half2*>(&v1.z));
        a2.x = fmaf(pp.y, f.x, a2.x); a2.y = fmaf(pp.y, f.y, a2.y);
        f = __half22float2(*reinterpret_cast<const __half2*>(&v1.w));
        a3.x = fmaf(pp.y, f.x, a3.x); a3.y = fmaf(pp.y, f.y, a3.y);
    }
    if (i < degc) {
        const float p0 = pw[i];
        const uint4 v0 = hrow[nbp[i] * 32];
        float2 f;
        f = __half22float2(*reinterpret_cast<const __half2*>(&v0.x));
        a0.x = fmaf(p0, f.x, a0.x); a0.y = fmaf(p0, f.y, a0.y);
        f = __half22float2(*reinterpret_cast<const __half2*>(&v0.y));
        a1.x = fmaf(p0, f.x, a1.x); a1.y = fmaf(p0, f.y, a1.y);
        f = __half22float2(*reinterpret_cast<const __half2*>(&v0.z));
        a2.x = fmaf(p0, f.x, a2.x); a2.y = fmaf(p0, f.y, a2.y);
        f = __half22float2(*reinterpret_cast<const __half2*>(&v0.w));
        a3.x = fmaf(p0, f.x, a3.x); a3.y = fmaf(p0, f.y, a3.y);
        i++;
    }
    // tail beyond smem capacity: recompute p on the fly (statistically never)
    for (i = degc; i < deg; i++) {
        const int m0 = g_nbrs[n * MAXD + i];
        float4 sdv = sd4[bN + m0];
        float e = ((head & 2) ? ((head & 1) ? c4.w + sdv.w : c4.z + sdv.z)
                              : ((head & 1) ? c4.y + sdv.y : c4.x + sdv.x));
        e = fmaxf(e, 0.2f * e);
        const float p0 = __expf(e);
        const uint4 v0 = hrow[m0 * 32];
        float2 f;
        f = __half22float2(*reinterpret_cast<const __half2*>(&v0.x));
        a0.x = fmaf(p0, f.x, a0.x); a0.y = fmaf(p0, f.y, a0.y);
        f = __half22float2(*reinterpret_cast<const __half2*>(&v0.y));
        a1.x = fmaf(p0, f.x, a1.x); a1.y = fmaf(p0, f.y, a1.y);
        f = __half22float2(*reinterpret_cast<const __half2*>(&v0.z));
        a2.x = fmaf(p0, f.x, a2.x); a2.y = fmaf(p0, f.y, a2.y);
        f = __half22float2(*reinterpret_cast<const __half2*>(&v0.w));
        a3.x = fmaf(p0, f.x, a3.x); a3.y = fmaf(p0, f.y, a3.y);
    }

    float4 o0 = make_float4(a0.x * invh, a0.y * invh, a1.x * invh, a1.y * invh);
    float4 o1 = make_float4(a2.x * invh, a2.y * invh, a3.x * invh, a3.y * invh);
    float4* outp = reinterpret_cast<float4*>(out);
    outp[bn * 64 + lane * 2 + 0] = o0;
    outp[bn * 64 + lane * 2 + 1] = o1;
}

// ---------------------------------------------------------------------------
extern "C" void kernel_launch(void* const* d_in, const int* in_sizes, int n_in,
                              void* d_out, int out_size)
{
    const float* x     = (const float*)d_in[0];
    const float* adj   = (const float*)d_in[1];
    const float* W     = (const float*)d_in[2];
    const float* a_src = (const float*)d_in[3];
    const float* a_dst = (const float*)d_in[4];
    float* out = (float*)d_out;

    fused_gemm_csr<<<GEMM_BLOCKS + N_, 256>>>(x, W, a_src, a_dst, adj);
    attn_kernel<<<N_ / ATT_NPB, 256>>>(out);
}

// round 7
// speedup vs baseline: 1.8551x; 1.1586x over previous
#include <cuda_runtime.h>
#include <cuda_bf16.h>
#include <cuda_fp16.h>
#include <cstdint>

#define B_   2
#define N_   4096
#define INF_ 256
#define H_   4
#define F_   64
#define BN_  (B_ * N_)      // 8192
#define HF_  (H_ * F_)      // 256
#define MAXD   512
#define MAXD_S 128          // smem capacity (deg mean ~82, P(>128)~1e-7; tail fallback correct)
#define PSTR   (MAXD_S + 4) // 132: bank-shift 4 words per head -> conflict-free float4 LDS

#define GEMM_BLOCKS 256     // (BN_/GBM) * (HF_/GBN) = 64*4

// ---------------- scratch (device globals) ----------------------------------
__device__ __align__(16) __half g_h16[BN_ * HF_];
__device__ __align__(16) float  g_ssrc[BN_ * H_];
__device__ __align__(16) float  g_sdst[BN_ * H_];
__device__ int g_nbrs[N_ * MAXD];
__device__ int g_deg[N_];

// ---------------------------------------------------------------------------
__device__ __forceinline__ float to_tf32(float a) {
    uint32_t u;
    asm("cvt.rna.tf32.f32 %0, %1;" : "=r"(u) : "f"(a));
    return __uint_as_float(u);
}

__device__ __forceinline__ void mma_tf32(float c[4],
                                         uint32_t a0, uint32_t a1, uint32_t a2, uint32_t a3,
                                         uint32_t b0, uint32_t b1)
{
    asm volatile(
        "mma.sync.aligned.m16n8k8.row.col.f32.tf32.tf32.f32 "
        "{%0,%1,%2,%3},{%4,%5,%6,%7},{%8,%9},{%0,%1,%2,%3};"
        : "+f"(c[0]), "+f"(c[1]), "+f"(c[2]), "+f"(c[3])
        : "r"(a0), "r"(a1), "r"(a2), "r"(a3), "r"(b0), "r"(b1));
}

// ---------------------------------------------------------------------------
// Kernel 1 (fused): blocks [0,256) = TF32 GEMM + s epilogue; blocks
// [256,256+4096) = adjacency scan. Unchanged from R5/R6.
// ---------------------------------------------------------------------------
#define GBM 128
#define GBN 64
#define GBK 32
#define GPAD 36
#define KITERS (INF_ / GBK)   // 8

__global__ __launch_bounds__(256) void fused_gemm_csr(const float* __restrict__ x,
                                                      const float* __restrict__ W,
                                                      const float* __restrict__ a_src,
                                                      const float* __restrict__ a_dst,
                                                      const float* __restrict__ adj)
{
    __shared__ float As[2][GBM][GPAD];
    __shared__ float Bs[2][GBN][GPAD];
    __shared__ float sS[GBM], sD[GBM];
    __shared__ int cnt;

    const int bid = blockIdx.x;
    const int t   = threadIdx.x;

    // ================= CSR path =================
    if (bid >= GEMM_BLOCKS) {
        const int n = bid - GEMM_BLOCKS;
        if (t == 0) cnt = 0;
        __syncthreads();
        const float4* row4 = reinterpret_cast<const float4*>(adj + (long long)n * N_);
#pragma unroll 4
        for (int i = t; i < N_ / 4; i += 256) {
            float4 v = row4[i];
            if (v.x != 0.0f) { int p = atomicAdd(&cnt, 1); if (p < MAXD) g_nbrs[n * MAXD + p] = i * 4 + 0; }
            if (v.y != 0.0f) { int p = atomicAdd(&cnt, 1); if (p < MAXD) g_nbrs[n * MAXD + p] = i * 4 + 1; }
            if (v.z != 0.0f) { int p = atomicAdd(&cnt, 1); if (p < MAXD) g_nbrs[n * MAXD + p] = i * 4 + 2; }
            if (v.w != 0.0f) { int p = atomicAdd(&cnt, 1); if (p < MAXD) g_nbrs[n * MAXD + p] = i * 4 + 3; }
        }
        __syncthreads();
        if (t == 0) g_deg[n] = cnt < MAXD ? cnt : MAXD;
        return;
    }

    // ================= GEMM path =================
    const int head = bid & 3;
    const int bm   = (bid >> 2) * GBM;
    const int bo   = head * GBN;

    const int lane = t & 31;
    const int warp = t >> 5;
    const int wm   = warp >> 2;
    const int wn   = warp & 3;

    if (t < GBM) { sS[t] = 0.0f; sD[t] = 0.0f; }

    float acc[4][2][4];
#pragma unroll
    for (int mt = 0; mt < 4; mt++)
#pragma unroll
        for (int nt = 0; nt < 2; nt++)
#pragma unroll
            for (int i = 0; i < 4; i++) acc[mt][nt][i] = 0.0f;

    const int arow = t >> 3;
    const int acol = (t & 7) * 4;

    float4 ar[4], br[2];

#pragma unroll
    for (int j = 0; j < 4; j++)
        ar[j] = *reinterpret_cast<const float4*>(&x[(bm + arow + 32 * j) * INF_ + acol]);
#pragma unroll
    for (int j = 0; j < 2; j++)
        br[j] = *reinterpret_cast<const float4*>(&W[(bo + arow + 32 * j) * INF_ + acol]);
#pragma unroll
    for (int j = 0; j < 4; j++) {
        const int r = arow + 32 * j;
        As[0][r][acol + 0] = to_tf32(ar[j].x);
        As[0][r][acol + 1] = to_tf32(ar[j].y);
        As[0][r][acol + 2] = to_tf32(ar[j].z);
        As[0][r][acol + 3] = to_tf32(ar[j].w);
    }
#pragma unroll
    for (int j = 0; j < 2; j++) {
        const int r = arow + 32 * j;
        Bs[0][r][acol + 0] = to_tf32(br[j].x);
        Bs[0][r][acol + 1] = to_tf32(br[j].y);
        Bs[0][r][acol + 2] = to_tf32(br[j].z);
        Bs[0][r][acol + 3] = to_tf32(br[j].w);
    }
    __syncthreads();

#pragma unroll
    for (int kt = 0; kt < KITERS; kt++) {
        const int cur = kt & 1;
        const int nxt = cur ^ 1;

        if (kt + 1 < KITERS) {
            const int k0 = (kt + 1) * GBK;
#pragma unroll
            for (int j = 0; j < 4; j++)
                ar[j] = *reinterpret_cast<const float4*>(&x[(bm + arow + 32 * j) * INF_ + k0 + acol]);
#pragma unroll
            for (int j = 0; j < 2; j++)
                br[j] = *reinterpret_cast<const float4*>(&W[(bo + arow + 32 * j) * INF_ + k0 + acol]);
        }

#pragma unroll
        for (int ks = 0; ks < 4; ks++) {
            const int kc = ks * 8 + (lane & 3);
            uint32_t Af[4][4];
#pragma unroll
            for (int mt = 0; mt < 4; mt++) {
                const int r0 = wm * 64 + mt * 16 + (lane >> 2);
                Af[mt][0] = __float_as_uint(As[cur][r0][kc]);
                Af[mt][1] = __float_as_uint(As[cur][r0 + 8][kc]);
                Af[mt][2] = __float_as_uint(As[cur][r0][kc + 4]);
                Af[mt][3] = __float_as_uint(As[cur][r0 + 8][kc + 4]);
            }
            uint32_t Bf[2][2];
#pragma unroll
            for (int nt = 0; nt < 2; nt++) {
                const int n0 = wn * 16 + nt * 8 + (lane >> 2);
                Bf[nt][0] = __float_as_uint(Bs[cur][n0][kc]);
                Bf[nt][1] = __float_as_uint(Bs[cur][n0][kc + 4]);
            }
#pragma unroll
            for (int mt = 0; mt < 4; mt++)
#pragma unroll
                for (int nt = 0; nt < 2; nt++)
                    mma_tf32(acc[mt][nt], Af[mt][0], Af[mt][1], Af[mt][2], Af[mt][3],
                             Bf[nt][0], Bf[nt][1]);
        }

        if (kt + 1 < KITERS) {
#pragma unroll
            for (int j = 0; j < 4; j++) {
                const int r = arow + 32 * j;
                As[nxt][r][acol + 0] = to_tf32(ar[j].x);
                As[nxt][r][acol + 1] = to_tf32(ar[j].y);
                As[nxt][r][acol + 2] = to_tf32(ar[j].z);
                As[nxt][r][acol + 3] = to_tf32(ar[j].w);
            }
#pragma unroll
            for (int j = 0; j < 2; j++) {
                const int r = arow + 32 * j;
                Bs[nxt][r][acol + 0] = to_tf32(br[j].x);
                Bs[nxt][r][acol + 1] = to_tf32(br[j].y);
                Bs[nxt][r][acol + 2] = to_tf32(br[j].z);
                Bs[nxt][r][acol + 3] = to_tf32(br[j].w);
            }
            __syncthreads();
        }
    }

#pragma unroll
    for (int mt = 0; mt < 4; mt++) {
#pragma unroll
        for (int nt = 0; nt < 2; nt++) {
            const int row = bm + wm * 64 + mt * 16 + (lane >> 2);
            const int col = bo + wn * 16 + nt * 8 + (lane & 3) * 2;
            float2 v0 = make_float2(acc[mt][nt][0], acc[mt][nt][1]);
            float2 v1 = make_float2(acc[mt][nt][2], acc[mt][nt][3]);
            *reinterpret_cast<__half2*>(&g_h16[row * HF_ + col]) = __float22half2_rn(v0);
            *reinterpret_cast<__half2*>(&g_h16[(row + 8) * HF_ + col]) = __float22half2_rn(v1);
        }
    }

    float asv[2][2], adv[2][2];
#pragma unroll
    for (int nt = 0; nt < 2; nt++)
#pragma unroll
        for (int j = 0; j < 2; j++) {
            const int c = wn * 16 + nt * 8 + (lane & 3) * 2 + j;
            asv[nt][j] = a_src[head * F_ + c];
            adv[nt][j] = a_dst[head * F_ + c];
        }

    __syncthreads();
#pragma unroll
    for (int mt = 0; mt < 4; mt++) {
        float ps0 = 0.f, ps1 = 0.f, pd0 = 0.f, pd1 = 0.f;
#pragma unroll
        for (int nt = 0; nt < 2; nt++) {
            ps0 = fmaf(acc[mt][nt][0], asv[nt][0], ps0);
            ps0 = fmaf(acc[mt][nt][1], asv[nt][1], ps0);
            ps1 = fmaf(acc[mt][nt][2], asv[nt][0], ps1);
            ps1 = fmaf(acc[mt][nt][3], asv[nt][1], ps1);
            pd0 = fmaf(acc[mt][nt][0], adv[nt][0], pd0);
            pd0 = fmaf(acc[mt][nt][1], adv[nt][1], pd0);
            pd1 = fmaf(acc[mt][nt][2], adv[nt][0], pd1);
            pd1 = fmaf(acc[mt][nt][3], adv[nt][1], pd1);
        }
#pragma unroll
        for (int o = 1; o < 4; o <<= 1) {
            ps0 += __shfl_xor_sync(0xFFFFFFFFu, ps0, o);
            ps1 += __shfl_xor_sync(0xFFFFFFFFu, ps1, o);
            pd0 += __shfl_xor_sync(0xFFFFFFFFu, pd0, o);
            pd1 += __shfl_xor_sync(0xFFFFFFFFu, pd1, o);
        }
        if ((lane & 3) == 0) {
            const int r = wm * 64 + mt * 16 + (lane >> 2);
            atomicAdd(&sS[r], ps0);
            atomicAdd(&sS[r + 8], ps1);
            atomicAdd(&sD[r], pd0);
            atomicAdd(&sD[r + 8], pd1);
        }
    }
    __syncthreads();
    if (t < GBM) {
        g_ssrc[(bm + t) * H_ + head] = sS[t];
        g_sdst[(bm + t) * H_ + head] = sD[t];
    }
}

// ---------------------------------------------------------------------------
// attn helpers
// ---------------------------------------------------------------------------
__device__ __forceinline__ void accum_row(float2& a0, float2& a1, float2& a2, float2& a3,
                                          float p, const uint4& v)
{
    float2 f;
    f = __half22float2(*reinterpret_cast<const __half2*>(&v.x));
    a0.x = fmaf(p, f.x, a0.x); a0.y = fmaf(p, f.y, a0.y);
    f = __half22float2(*reinterpret_cast<const __half2*>(&v.y));
    a1.x = fmaf(p, f.x, a1.x); a1.y = fmaf(p, f.y, a1.y);
    f = __half22float2(*reinterpret_cast<const __half2*>(&v.z));
    a2.x = fmaf(p, f.x, a2.x); a2.y = fmaf(p, f.y, a2.y);
    f = __half22float2(*reinterpret_cast<const __half2*>(&v.w));
    a3.x = fmaf(p, f.x, a3.x); a3.y = fmaf(p, f.y, a3.y);
}

// ---------------------------------------------------------------------------
// Kernel 2 (attn v5): warp = one (b,n), all 4 heads.
// Phase 1: strided exp (deg/32 float4 s_dst gathers, 4 exps each),
//          p stored head-major with PSTR=132 padding (conflict-free).
// Phase 2: gather unrolled x4, 4 LDG.128 front-batched (MLP 4).
// ---------------------------------------------------------------------------
#define ATT_NPB 4   // n's per block; 8 warps = {b0,b1} x {n0..n3}

__global__ __launch_bounds__(256, 5) void attn_kernel(float* __restrict__ out)
{
    __shared__ __align__(16) int   nbS[ATT_NPB][MAXD_S];
    __shared__ __align__(16) float pS[8][H_ * PSTR];
    __shared__ int degS[ATT_NPB];

    const int t    = threadIdx.x;
    const int w    = t >> 5;
    const int lane = t & 31;
    const int b    = w & 1;
    const int nsub = w >> 1;
    const int n    = blockIdx.x * ATT_NPB + nsub;
    const int bn   = b * N_ + n;

    if (b == 0) {
        if (lane == 0) degS[nsub] = g_deg[n];
        const int dg = g_deg[n];
        for (int i = lane; i < dg && i < MAXD_S; i += 32)
            nbS[nsub][i] = g_nbrs[n * MAXD + i];
    }
    __syncthreads();

    const int deg  = degS[nsub];
    const int degc = deg < MAXD_S ? deg : MAXD_S;
    const int bN   = b * N_;

    const float4 c4 = *reinterpret_cast<const float4*>(&g_ssrc[bn * H_]);
    const float4* __restrict__ sd4 = reinterpret_cast<const float4*>(g_sdst);

    // ---- phase 1: strided p computation (all heads), padded head-major smem
    float4 sum4 = make_float4(0.f, 0.f, 0.f, 0.f);
    for (int i = lane; i < degc; i += 32) {
        const int m = nbS[nsub][i];
        float4 sdv = sd4[bN + m];
        float ex = c4.x + sdv.x, ey = c4.y + sdv.y, ez = c4.z + sdv.z, ew = c4.w + sdv.w;
        ex = fmaxf(ex, 0.2f * ex);
        ey = fmaxf(ey, 0.2f * ey);
        ez = fmaxf(ez, 0.2f * ez);
        ew = fmaxf(ew, 0.2f * ew);
        float px = __expf(ex), py = __expf(ey), pz = __expf(ez), pw = __expf(ew);
        pS[w][0 * PSTR + i] = px;
        pS[w][1 * PSTR + i] = py;
        pS[w][2 * PSTR + i] = pz;
        pS[w][3 * PSTR + i] = pw;
        sum4.x += px; sum4.y += py; sum4.z += pz; sum4.w += pw;
    }
    for (int i = degc + lane; i < deg; i += 32) {
        const int m = g_nbrs[n * MAXD + i];
        float4 sdv = sd4[bN + m];
        float ex = c4.x + sdv.x, ey = c4.y + sdv.y, ez = c4.z + sdv.z, ew = c4.w + sdv.w;
        ex = fmaxf(ex, 0.2f * ex);
        ey = fmaxf(ey, 0.2f * ey);
        ez = fmaxf(ez, 0.2f * ez);
        ew = fmaxf(ew, 0.2f * ew);
        sum4.x += __expf(ex); sum4.y += __expf(ey); sum4.z += __expf(ez); sum4.w += __expf(ew);
    }
#pragma unroll
    for (int o = 16; o > 0; o >>= 1) {
        sum4.x += __shfl_xor_sync(0xFFFFFFFFu, sum4.x, o);
        sum4.y += __shfl_xor_sync(0xFFFFFFFFu, sum4.y, o);
        sum4.z += __shfl_xor_sync(0xFFFFFFFFu, sum4.z, o);
        sum4.w += __shfl_xor_sync(0xFFFFFFFFu, sum4.w, o);
    }

    const int head = lane >> 3;
    float invh = (head & 2) ? ((head & 1) ? sum4.w : sum4.z)
                            : ((head & 1) ? sum4.y : sum4.x);
    invh = 1.0f / invh;

    __syncwarp();

    // ---- phase 2: gather + weighted accumulate, unrolled x4 (MLP 4)
    const uint4* __restrict__ hrow = reinterpret_cast<const uint4*>(g_h16) + (long long)bN * 32 + lane;
    const float* __restrict__ pw = &pS[w][head * PSTR];
    const int*   __restrict__ nbp = &nbS[nsub][0];

    float2 a0 = make_float2(0.f, 0.f), a1 = a0, a2 = a0, a3 = a0;

    int i = 0;
    for (; i + 4 <= degc; i += 4) {
        const int4   mm = *reinterpret_cast<const int4*>(&nbp[i]);
        const float4 pp = *reinterpret_cast<const float4*>(&pw[i]);
        const uint4 v0 = hrow[mm.x * 32];
        const uint4 v1 = hrow[mm.y * 32];
        const uint4 v2 = hrow[mm.z * 32];
        const uint4 v3 = hrow[mm.w * 32];
        accum_row(a0, a1, a2, a3, pp.x, v0);
        accum_row(a0, a1, a2, a3, pp.y, v1);
        accum_row(a0, a1, a2, a3, pp.z, v2);
        accum_row(a0, a1, a2, a3, pp.w, v3);
    }
    for (; i < degc; i++) {
        const float p0 = pw[i];
        const uint4 v0 = hrow[nbp[i] * 32];
        accum_row(a0, a1, a2, a3, p0, v0);
    }
    // tail beyond smem capacity: recompute p on the fly (statistically never)
    for (i = degc; i < deg; i++) {
        const int m0 = g_nbrs[n * MAXD + i];
        float4 sdv = sd4[bN + m0];
        float e = ((head & 2) ? ((head & 1) ? c4.w + sdv.w : c4.z + sdv.z)
                              : ((head & 1) ? c4.y + sdv.y : c4.x + sdv.x));
        e = fmaxf(e, 0.2f * e);
        const float p0 = __expf(e);
        const uint4 v0 = hrow[m0 * 32];
        accum_row(a0, a1, a2, a3, p0, v0);
    }

    float4 o0 = make_float4(a0.x * invh, a0.y * invh, a1.x * invh, a1.y * invh);
    float4 o1 = make_float4(a2.x * invh, a2.y * invh, a3.x * invh, a3.y * invh);
    float4* outp = reinterpret_cast<float4*>(out);
    outp[bn * 64 + lane * 2 + 0] = o0;
    outp[bn * 64 + lane * 2 + 1] = o1;
}

// ---------------------------------------------------------------------------
extern "C" void kernel_launch(void* const* d_in, const int* in_sizes, int n_in,
                              void* d_out, int out_size)
{
    const float* x     = (const float*)d_in[0];
    const float* adj   = (const float*)d_in[1];
    const float* W     = (const float*)d_in[2];
    const float* a_src = (const float*)d_in[3];
    const float* a_dst = (const float*)d_in[4];
    float* out = (float*)d_out;

    fused_gemm_csr<<<GEMM_BLOCKS + N_, 256>>>(x, W, a_src, a_dst, adj);
    attn_kernel<<<N_ / ATT_NPB, 256>>>(out);
}

// round 9
// speedup vs baseline: 1.8869x; 1.0171x over previous
#include <cuda_runtime.h>
#include <cuda_bf16.h>
#include <cuda_fp16.h>
#include <cstdint>

#define B_   2
#define N_   4096
#define INF_ 256
#define H_   4
#define F_   64
#define BN_  (B_ * N_)      // 8192
#define HF_  (H_ * F_)      // 256
#define MAXD   512
#define MAXD_S 128          // smem capacity (deg mean ~82, P(>128)~1e-7; tail fallback correct)
#define PSTR   (MAXD_S + 4) // 132: bank-shift 4 words per head -> conflict-free float4 LDS

#define GEMM_BLOCKS 256     // (BN_/GBM) * (HF_/GBN) = 64*4

// ---------------- scratch (device globals) ----------------------------------
__device__ __align__(16) __half g_h16[BN_ * HF_];
__device__ __align__(16) float  g_ssrc[BN_ * H_];
__device__ __align__(16) float  g_sdst[BN_ * H_];
__device__ int g_nbrs[N_ * MAXD];
__device__ int g_deg[N_];

// ---------------------------------------------------------------------------
__device__ __forceinline__ uint32_t tf32_rna(float a) {
    uint32_t u;
    asm("cvt.rna.tf32.f32 %0, %1;" : "=r"(u) : "f"(a));
    return u;
}

__device__ __forceinline__ void mma_tf32(float c[4],
                                         uint32_t a0, uint32_t a1, uint32_t a2, uint32_t a3,
                                         uint32_t b0, uint32_t b1)
{
    asm volatile(
        "mma.sync.aligned.m16n8k8.row.col.f32.tf32.tf32.f32 "
        "{%0,%1,%2,%3},{%4,%5,%6,%7},{%8,%9},{%0,%1,%2,%3};"
        : "+f"(c[0]), "+f"(c[1]), "+f"(c[2]), "+f"(c[3])
        : "r"(a0), "r"(a1), "r"(a2), "r"(a3), "r"(b0), "r"(b1));
}

__device__ __forceinline__ void cp16(uint32_t dst_smem, const void* src) {
    asm volatile("cp.async.cg.shared.global [%0], [%1], 16;" :: "r"(dst_smem), "l"(src));
}
__device__ __forceinline__ void cp_commit() {
    asm volatile("cp.async.commit_group;");
}
__device__ __forceinline__ void cp_wait_all() {
    asm volatile("cp.async.wait_group 0;");
}

// ---------------------------------------------------------------------------
// Kernel 1 (fused): blocks [0,256) = TF32 GEMM (cp.async double-buffered,
// rna conversion at fragment-load time -> R7-identical numerics); blocks
// [256,256+4096) = adjacency scan. launch_bounds(256,4) keeps 4 blocks/SM.
// ---------------------------------------------------------------------------
#define GBM 128
#define GBN 64
#define GBK 32
#define GPAD 36
#define KITERS (INF_ / GBK)   // 8

__global__ __launch_bounds__(256, 4) void fused_gemm_csr(const float* __restrict__ x,
                                                         const float* __restrict__ W,
                                                         const float* __restrict__ a_src,
                                                         const float* __restrict__ a_dst,
                                                         const float* __restrict__ adj)
{
    __shared__ __align__(16) float As[2][GBM][GPAD];
    __shared__ __align__(16) float Bs[2][GBN][GPAD];
    __shared__ float sS[GBM], sD[GBM];
    __shared__ int cnt;

    const int bid = blockIdx.x;
    const int t   = threadIdx.x;

    // ================= CSR path =================
    if (bid >= GEMM_BLOCKS) {
        const int n = bid - GEMM_BLOCKS;
        if (t == 0) cnt = 0;
        __syncthreads();
        const float4* row4 = reinterpret_cast<const float4*>(adj + (long long)n * N_);
#pragma unroll 4
        for (int i = t; i < N_ / 4; i += 256) {
            float4 v = row4[i];
            if (v.x != 0.0f) { int p = atomicAdd(&cnt, 1); if (p < MAXD) g_nbrs[n * MAXD + p] = i * 4 + 0; }
            if (v.y != 0.0f) { int p = atomicAdd(&cnt, 1); if (p < MAXD) g_nbrs[n * MAXD + p] = i * 4 + 1; }
            if (v.z != 0.0f) { int p = atomicAdd(&cnt, 1); if (p < MAXD) g_nbrs[n * MAXD + p] = i * 4 + 2; }
            if (v.w != 0.0f) { int p = atomicAdd(&cnt, 1); if (p < MAXD) g_nbrs[n * MAXD + p] = i * 4 + 3; }
        }
        __syncthreads();
        if (t == 0) g_deg[n] = cnt < MAXD ? cnt : MAXD;
        return;
    }

    // ================= GEMM path =================
    const int head = bid & 3;
    const int bm   = (bid >> 2) * GBM;
    const int bo   = head * GBN;

    const int lane = t & 31;
    const int warp = t >> 5;
    const int wm   = warp >> 2;
    const int wn   = warp & 3;

    if (t < GBM) { sS[t] = 0.0f; sD[t] = 0.0f; }

    float acc[4][2][4];
#pragma unroll
    for (int mt = 0; mt < 4; mt++)
#pragma unroll
        for (int nt = 0; nt < 2; nt++)
#pragma unroll
            for (int i = 0; i < 4; i++) acc[mt][nt][i] = 0.0f;

    const int arow = t >> 3;          // 0..31
    const int acol = (t & 7) * 4;     // float offset (16B granules)

    uint32_t asA[2][4], asB[2][2];
#pragma unroll
    for (int bufi = 0; bufi < 2; bufi++) {
#pragma unroll
        for (int j = 0; j < 4; j++)
            asA[bufi][j] = (uint32_t)__cvta_generic_to_shared(&As[bufi][arow + 32 * j][acol]);
#pragma unroll
        for (int j = 0; j < 2; j++)
            asB[bufi][j] = (uint32_t)__cvta_generic_to_shared(&Bs[bufi][arow + 32 * j][acol]);
    }

    // prologue: stage tile 0
#pragma unroll
    for (int j = 0; j < 4; j++)
        cp16(asA[0][j], &x[(bm + arow + 32 * j) * INF_ + acol]);
#pragma unroll
    for (int j = 0; j < 2; j++)
        cp16(asB[0][j], &W[(bo + arow + 32 * j) * INF_ + acol]);
    cp_commit();

#pragma unroll
    for (int kt = 0; kt < KITERS; kt++) {
        const int cur = kt & 1;
        const int nxt = cur ^ 1;

        cp_wait_all();
        __syncthreads();

        if (kt + 1 < KITERS) {
            const int k0 = (kt + 1) * GBK;
#pragma unroll
            for (int j = 0; j < 4; j++)
                cp16(asA[nxt][j], &x[(bm + arow + 32 * j) * INF_ + k0 + acol]);
#pragma unroll
            for (int j = 0; j < 2; j++)
                cp16(asB[nxt][j], &W[(bo + arow + 32 * j) * INF_ + k0 + acol]);
            cp_commit();
        }

        // compute on current buffer; rna-convert fragments AFTER the LDS
#pragma unroll
        for (int ks = 0; ks < 4; ks++) {
            const int kc = ks * 8 + (lane & 3);
            uint32_t Af[4][4];
#pragma unroll
            for (int mt = 0; mt < 4; mt++) {
                const int r0 = wm * 64 + mt * 16 + (lane >> 2);
                Af[mt][0] = tf32_rna(As[cur][r0][kc]);
                Af[mt][1] = tf32_rna(As[cur][r0 + 8][kc]);
                Af[mt][2] = tf32_rna(As[cur][r0][kc + 4]);
                Af[mt][3] = tf32_rna(As[cur][r0 + 8][kc + 4]);
            }
            uint32_t Bf[2][2];
#pragma unroll
            for (int nt = 0; nt < 2; nt++) {
                const int n0 = wn * 16 + nt * 8 + (lane >> 2);
                Bf[nt][0] = tf32_rna(Bs[cur][n0][kc]);
                Bf[nt][1] = tf32_rna(Bs[cur][n0][kc + 4]);
            }
#pragma unroll
            for (int mt = 0; mt < 4; mt++)
#pragma unroll
                for (int nt = 0; nt < 2; nt++)
                    mma_tf32(acc[mt][nt], Af[mt][0], Af[mt][1], Af[mt][2], Af[mt][3],
                             Bf[nt][0], Bf[nt][1]);
        }
    }

    // ---- epilogue A: fp16 h stores
#pragma unroll
    for (int mt = 0; mt < 4; mt++) {
#pragma unroll
        for (int nt = 0; nt < 2; nt++) {
            const int row = bm + wm * 64 + mt * 16 + (lane >> 2);
            const int col = bo + wn * 16 + nt * 8 + (lane & 3) * 2;
            float2 v0 = make_float2(acc[mt][nt][0], acc[mt][nt][1]);
            float2 v1 = make_float2(acc[mt][nt][2], acc[mt][nt][3]);
            *reinterpret_cast<__half2*>(&g_h16[row * HF_ + col]) = __float22half2_rn(v0);
            *reinterpret_cast<__half2*>(&g_h16[(row + 8) * HF_ + col]) = __float22half2_rn(v1);
        }
    }

    // ---- epilogue B: fused s_src/s_dst for this head
    float asv[2][2], adv[2][2];
#pragma unroll
    for (int nt = 0; nt < 2; nt++)
#pragma unroll
        for (int j = 0; j < 2; j++) {
            const int c = wn * 16 + nt * 8 + (lane & 3) * 2 + j;
            asv[nt][j] = a_src[head * F_ + c];
            adv[nt][j] = a_dst[head * F_ + c];
        }

    __syncthreads();
#pragma unroll
    for (int mt = 0; mt < 4; mt++) {
        float ps0 = 0.f, ps1 = 0.f, pd0 = 0.f, pd1 = 0.f;
#pragma unroll
        for (int nt = 0; nt < 2; nt++) {
            ps0 = fmaf(acc[mt][nt][0], asv[nt][0], ps0);
            ps0 = fmaf(acc[mt][nt][1], asv[nt][1], ps0);
            ps1 = fmaf(acc[mt][nt][2], asv[nt][0], ps1);
            ps1 = fmaf(acc[mt][nt][3], asv[nt][1], ps1);
            pd0 = fmaf(acc[mt][nt][0], adv[nt][0], pd0);
            pd0 = fmaf(acc[mt][nt][1], adv[nt][1], pd0);
            pd1 = fmaf(acc[mt][nt][2], adv[nt][0], pd1);
            pd1 = fmaf(acc[mt][nt][3], adv[nt][1], pd1);
        }
#pragma unroll
        for (int o = 1; o < 4; o <<= 1) {
            ps0 += __shfl_xor_sync(0xFFFFFFFFu, ps0, o);
            ps1 += __shfl_xor_sync(0xFFFFFFFFu, ps1, o);
            pd0 += __shfl_xor_sync(0xFFFFFFFFu, pd0, o);
            pd1 += __shfl_xor_sync(0xFFFFFFFFu, pd1, o);
        }
        if ((lane & 3) == 0) {
            const int r = wm * 64 + mt * 16 + (lane >> 2);
            atomicAdd(&sS[r], ps0);
            atomicAdd(&sS[r + 8], ps1);
            atomicAdd(&sD[r], pd0);
            atomicAdd(&sD[r + 8], pd1);
        }
    }
    __syncthreads();
    if (t < GBM) {
        g_ssrc[(bm + t) * H_ + head] = sS[t];
        g_sdst[(bm + t) * H_ + head] = sD[t];
    }
}

// ---------------------------------------------------------------------------
__device__ __forceinline__ void accum_row(float2& a0, float2& a1, float2& a2, float2& a3,
                                          float p, const uint4& v)
{
    float2 f;
    f = __half22float2(*reinterpret_cast<const __half2*>(&v.x));
    a0.x = fmaf(p, f.x, a0.x); a0.y = fmaf(p, f.y, a0.y);
    f = __half22float2(*reinterpret_cast<const __half2*>(&v.y));
    a1.x = fmaf(p, f.x, a1.x); a1.y = fmaf(p, f.y, a1.y);
    f = __half22float2(*reinterpret_cast<const __half2*>(&v.z));
    a2.x = fmaf(p, f.x, a2.x); a2.y = fmaf(p, f.y, a2.y);
    f = __half22float2(*reinterpret_cast<const __half2*>(&v.w));
    a3.x = fmaf(p, f.x, a3.x); a3.y = fmaf(p, f.y, a3.y);
}

// ---------------------------------------------------------------------------
// Kernel 2 (attn v6): R7 algorithm, 128-thread blocks (ATT_NPB=2),
// smem 9.4KB, launch_bounds(128,10) -> 40 warps/SM, grid 2048.
// ---------------------------------------------------------------------------
#define ATT_NPB 2   // n's per block; 4 warps = {b0,b1} x {n0,n1}

__global__ __launch_bounds__(128, 10) void attn_kernel(float* __restrict__ out)
{
    __shared__ __align__(16) int   nbS[ATT_NPB][MAXD_S];
    __shared__ __align__(16) float pS[4][H_ * PSTR];
    __shared__ int degS[ATT_NPB];

    const int t    = threadIdx.x;
    const int w    = t >> 5;
    const int lane = t & 31;
    const int b    = w & 1;
    const int nsub = w >> 1;
    const int n    = blockIdx.x * ATT_NPB + nsub;
    const int bn   = b * N_ + n;

    if (b == 0) {
        if (lane == 0) degS[nsub] = g_deg[n];
        const int dg = g_deg[n];
        for (int i = lane; i < dg && i < MAXD_S; i += 32)
            nbS[nsub][i] = g_nbrs[n * MAXD + i];
    }
    __syncthreads();

    const int deg  = degS[nsub];
    const int degc = deg < MAXD_S ? deg : MAXD_S;
    const int bN   = b * N_;

    const float4 c4 = *reinterpret_cast<const float4*>(&g_ssrc[bn * H_]);
    const float4* __restrict__ sd4 = reinterpret_cast<const float4*>(g_sdst);

    // ---- phase 1: strided p computation (all heads), padded head-major smem
    float4 sum4 = make_float4(0.f, 0.f, 0.f, 0.f);
    for (int i = lane; i < degc; i += 32) {
        const int m = nbS[nsub][i];
        float4 sdv = sd4[bN + m];
        float ex = c4.x + sdv.x, ey = c4.y + sdv.y, ez = c4.z + sdv.z, ew = c4.w + sdv.w;
        ex = fmaxf(ex, 0.2f * ex);
        ey = fmaxf(ey, 0.2f * ey);
        ez = fmaxf(ez, 0.2f * ez);
        ew = fmaxf(ew, 0.2f * ew);
        float px = __expf(ex), py = __expf(ey), pz = __expf(ez), pw = __expf(ew);
        pS[w][0 * PSTR + i] = px;
        pS[w][1 * PSTR + i] = py;
        pS[w][2 * PSTR + i] = pz;
        pS[w][3 * PSTR + i] = pw;
        sum4.x += px; sum4.y += py; sum4.z += pz; sum4.w += pw;
    }
    for (int i = degc + lane; i < deg; i += 32) {
        const int m = g_nbrs[n * MAXD + i];
        float4 sdv = sd4[bN + m];
        float ex = c4.x + sdv.x, ey = c4.y + sdv.y, ez = c4.z + sdv.z, ew = c4.w + sdv.w;
        ex = fmaxf(ex, 0.2f * ex);
        ey = fmaxf(ey, 0.2f * ey);
        ez = fmaxf(ez, 0.2f * ez);
        ew = fmaxf(ew, 0.2f * ew);
        sum4.x += __expf(ex); sum4.y += __expf(ey); sum4.z += __expf(ez); sum4.w += __expf(ew);
    }
#pragma unroll
    for (int o = 16; o > 0; o >>= 1) {
        sum4.x += __shfl_xor_sync(0xFFFFFFFFu, sum4.x, o);
        sum4.y += __shfl_xor_sync(0xFFFFFFFFu, sum4.y, o);
        sum4.z += __shfl_xor_sync(0xFFFFFFFFu, sum4.z, o);
        sum4.w += __shfl_xor_sync(0xFFFFFFFFu, sum4.w, o);
    }

    const int head = lane >> 3;
    float invh = (head & 2) ? ((head & 1) ? sum4.w : sum4.z)
                            : ((head & 1) ? sum4.y : sum4.x);
    invh = 1.0f / invh;

    __syncwarp();

    // ---- phase 2: gather + weighted accumulate, unrolled x4 (MLP 4)
    const uint4* __restrict__ hrow = reinterpret_cast<const uint4*>(g_h16) + (long long)bN * 32 + lane;
    const float* __restrict__ pw = &pS[w][head * PSTR];
    const int*   __restrict__ nbp = &nbS[nsub][0];

    float2 a0 = make_float2(0.f, 0.f), a1 = a0, a2 = a0, a3 = a0;

    int i = 0;
    for (; i + 4 <= degc; i += 4) {
        const int4   mm = *reinterpret_cast<const int4*>(&nbp[i]);
        const float4 pp = *reinterpret_cast<const float4*>(&pw[i]);
        const uint4 v0 = hrow[mm.x * 32];
        const uint4 v1 = hrow[mm.y * 32];
        const uint4 v2 = hrow[mm.z * 32];
        const uint4 v3 = hrow[mm.w * 32];
        accum_row(a0, a1, a2, a3, pp.x, v0);
        accum_row(a0, a1, a2, a3, pp.y, v1);
        accum_row(a0, a1, a2, a3, pp.z, v2);
        accum_row(a0, a1, a2, a3, pp.w, v3);
    }
    for (; i < degc; i++) {
        const float p0 = pw[i];
        const uint4 v0 = hrow[nbp[i] * 32];
        accum_row(a0, a1, a2, a3, p0, v0);
    }
    // tail beyond smem capacity: recompute p on the fly (statistically never)
    for (i = degc; i < deg; i++) {
        const int m0 = g_nbrs[n * MAXD + i];
        float4 sdv = sd4[bN + m0];
        float e = ((head & 2) ? ((head & 1) ? c4.w + sdv.w : c4.z + sdv.z)
                              : ((head & 1) ? c4.y + sdv.y : c4.x + sdv.x));
        e = fmaxf(e, 0.2f * e);
        const float p0 = __expf(e);
        const uint4 v0 = hrow[m0 * 32];
        accum_row(a0, a1, a2, a3, p0, v0);
    }

    float4 o0 = make_float4(a0.x * invh, a0.y * invh, a1.x * invh, a1.y * invh);
    float4 o1 = make_float4(a2.x * invh, a2.y * invh, a3.x * invh, a3.y * invh);
    float4* outp = reinterpret_cast<float4*>(out);
    outp[bn * 64 + lane * 2 + 0] = o0;
    outp[bn * 64 + lane * 2 + 1] = o1;
}

// ---------------------------------------------------------------------------
extern "C" void kernel_launch(void* const* d_in, const int* in_sizes, int n_in,
                              void* d_out, int out_size)
{
    const float* x     = (const float*)d_in[0];
    const float* adj   = (const float*)d_in[1];
    const float* W     = (const float*)d_in[2];
    const float* a_src = (const float*)d_in[3];
    const float* a_dst = (const float*)d_in[4];
    float* out = (float*)d_out;

    fused_gemm_csr<<<GEMM_BLOCKS + N_, 256>>>(x, W, a_src, a_dst, adj);
    attn_kernel<<<N_ / ATT_NPB, 128>>>(out);
}

// round 10
// speedup vs baseline: 1.9692x; 1.0436x over previous
#include <cuda_runtime.h>
#include <cuda_bf16.h>
#include <cuda_fp16.h>
#include <cstdint>

#define B_   2
#define N_   4096
#define INF_ 256
#define H_   4
#define F_   64
#define BN_  (B_ * N_)      // 8192
#define HF_  (H_ * F_)      // 256
#define MAXD   512
#define MAXD_S 128          // smem capacity (deg mean ~82, P(>128)~1e-7; tail fallback correct)
#define PSTR   (MAXD_S + 4) // 132: bank-shift -> conflict-free float4 LDS

#define GEMM_BLOCKS 256     // (BN_/GBM) * (HF_/GBN) = 64*4
#define CSR_BLOCKS  (N_ / 2)  // 2 adjacency rows per block
#define NGROUPS     (N_ / 2)  // attn work groups (ATT_NPB=2)
#define ATT_GRID    1520      // 152 SMs x 10 blocks: one full wave, ticket-fed

// ---------------- scratch (device globals) ----------------------------------
__device__ __align__(16) __half g_h16[BN_ * HF_];
__device__ __align__(16) float  g_ssrc[BN_ * H_];
__device__ __align__(16) float  g_sdst[BN_ * H_];
__device__ int g_nbrs[N_ * MAXD];
__device__ int g_deg[N_];
__device__ int g_ticket;

// ---------------------------------------------------------------------------
__device__ __forceinline__ uint32_t tf32_rna(float a) {
    uint32_t u;
    asm("cvt.rna.tf32.f32 %0, %1;" : "=r"(u) : "f"(a));
    return u;
}

__device__ __forceinline__ void mma_tf32(float c[4],
                                         uint32_t a0, uint32_t a1, uint32_t a2, uint32_t a3,
                                         uint32_t b0, uint32_t b1)
{
    asm volatile(
        "mma.sync.aligned.m16n8k8.row.col.f32.tf32.tf32.f32 "
        "{%0,%1,%2,%3},{%4,%5,%6,%7},{%8,%9},{%0,%1,%2,%3};"
        : "+f"(c[0]), "+f"(c[1]), "+f"(c[2]), "+f"(c[3])
        : "r"(a0), "r"(a1), "r"(a2), "r"(a3), "r"(b0), "r"(b1));
}

__device__ __forceinline__ void cp16(uint32_t dst_smem, const void* src) {
    asm volatile("cp.async.cg.shared.global [%0], [%1], 16;" :: "r"(dst_smem), "l"(src));
}
__device__ __forceinline__ void cp_commit() {
    asm volatile("cp.async.commit_group;");
}
__device__ __forceinline__ void cp_wait_all() {
    asm volatile("cp.async.wait_group 0;");
}

// ---------------------------------------------------------------------------
// Kernel 1 (fused): blocks [0,256) = TF32 GEMM (cp.async double-buffered,
// rna at fragment load); blocks [256,256+2048) = adjacency scan, 2 rows per
// block with 8 front-batched float4 loads per thread (MLP 8 -> DRAM BW-bound).
// Block 0 thread 0 also resets the attn work ticket.
// ---------------------------------------------------------------------------
#define GBM 128
#define GBN 64
#define GBK 32
#define GPAD 36
#define KITERS (INF_ / GBK)   // 8

__global__ __launch_bounds__(256, 4) void fused_gemm_csr(const float* __restrict__ x,
                                                         const float* __restrict__ W,
                                                         const float* __restrict__ a_src,
                                                         const float* __restrict__ a_dst,
                                                         const float* __restrict__ adj)
{
    __shared__ __align__(16) float As[2][GBM][GPAD];
    __shared__ __align__(16) float Bs[2][GBN][GPAD];
    __shared__ float sS[GBM], sD[GBM];
    __shared__ int cnt[2];

    const int bid = blockIdx.x;
    const int t   = threadIdx.x;

    if (bid == 0 && t == 0) g_ticket = 0;   // reset attn work queue

    // ================= CSR path: 2 rows per block =================
    if (bid >= GEMM_BLOCKS) {
        const int n0 = (bid - GEMM_BLOCKS) * 2;
        if (t < 2) cnt[t] = 0;
        __syncthreads();

        const int r  = t >> 7;        // 0/1: which row this thread scans
        const int tt = t & 127;       // lane within the row's 128-thread team
        const int n  = n0 + r;
        const float4* row4 = reinterpret_cast<const float4*>(adj + (long long)n * N_);

        // front-batch ALL 8 loads (MLP 8), then consume
        float4 v[8];
#pragma unroll
        for (int j = 0; j < 8; j++)
            v[j] = row4[tt + 128 * j];

#pragma unroll
        for (int j = 0; j < 8; j++) {
            const int base = (tt + 128 * j) * 4;
            if (v[j].x != 0.0f) { int p = atomicAdd(&cnt[r], 1); if (p < MAXD) g_nbrs[n * MAXD + p] = base + 0; }
            if (v[j].y != 0.0f) { int p = atomicAdd(&cnt[r], 1); if (p < MAXD) g_nbrs[n * MAXD + p] = base + 1; }
            if (v[j].z != 0.0f) { int p = atomicAdd(&cnt[r], 1); if (p < MAXD) g_nbrs[n * MAXD + p] = base + 2; }
            if (v[j].w != 0.0f) { int p = atomicAdd(&cnt[r], 1); if (p < MAXD) g_nbrs[n * MAXD + p] = base + 3; }
        }
        __syncthreads();
        if (t < 2) g_deg[n0 + t] = cnt[t] < MAXD ? cnt[t] : MAXD;
        return;
    }

    // ================= GEMM path (unchanged from R9) =================
    const int head = bid & 3;
    const int bm   = (bid >> 2) * GBM;
    const int bo   = head * GBN;

    const int lane = t & 31;
    const int warp = t >> 5;
    const int wm   = warp >> 2;
    const int wn   = warp & 3;

    if (t < GBM) { sS[t] = 0.0f; sD[t] = 0.0f; }

    float acc[4][2][4];
#pragma unroll
    for (int mt = 0; mt < 4; mt++)
#pragma unroll
        for (int nt = 0; nt < 2; nt++)
#pragma unroll
            for (int i = 0; i < 4; i++) acc[mt][nt][i] = 0.0f;

    const int arow = t >> 3;
    const int acol = (t & 7) * 4;

    uint32_t asA[2][4], asB[2][2];
#pragma unroll
    for (int bufi = 0; bufi < 2; bufi++) {
#pragma unroll
        for (int j = 0; j < 4; j++)
            asA[bufi][j] = (uint32_t)__cvta_generic_to_shared(&As[bufi][arow + 32 * j][acol]);
#pragma unroll
        for (int j = 0; j < 2; j++)
            asB[bufi][j] = (uint32_t)__cvta_generic_to_shared(&Bs[bufi][arow + 32 * j][acol]);
    }

#pragma unroll
    for (int j = 0; j < 4; j++)
        cp16(asA[0][j], &x[(bm + arow + 32 * j) * INF_ + acol]);
#pragma unroll
    for (int j = 0; j < 2; j++)
        cp16(asB[0][j], &W[(bo + arow + 32 * j) * INF_ + acol]);
    cp_commit();

#pragma unroll
    for (int kt = 0; kt < KITERS; kt++) {
        const int cur = kt & 1;
        const int nxt = cur ^ 1;

        cp_wait_all();
        __syncthreads();

        if (kt + 1 < KITERS) {
            const int k0 = (kt + 1) * GBK;
#pragma unroll
            for (int j = 0; j < 4; j++)
                cp16(asA[nxt][j], &x[(bm + arow + 32 * j) * INF_ + k0 + acol]);
#pragma unroll
            for (int j = 0; j < 2; j++)
                cp16(asB[nxt][j], &W[(bo + arow + 32 * j) * INF_ + k0 + acol]);
            cp_commit();
        }

#pragma unroll
        for (int ks = 0; ks < 4; ks++) {
            const int kc = ks * 8 + (lane & 3);
            uint32_t Af[4][4];
#pragma unroll
            for (int mt = 0; mt < 4; mt++) {
                const int r0 = wm * 64 + mt * 16 + (lane >> 2);
                Af[mt][0] = tf32_rna(As[cur][r0][kc]);
                Af[mt][1] = tf32_rna(As[cur][r0 + 8][kc]);
                Af[mt][2] = tf32_rna(As[cur][r0][kc + 4]);
                Af[mt][3] = tf32_rna(As[cur][r0 + 8][kc + 4]);
            }
            uint32_t Bf[2][2];
#pragma unroll
            for (int nt = 0; nt < 2; nt++) {
                const int n0 = wn * 16 + nt * 8 + (lane >> 2);
                Bf[nt][0] = tf32_rna(Bs[cur][n0][kc]);
                Bf[nt][1] = tf32_rna(Bs[cur][n0][kc + 4]);
            }
#pragma unroll
            for (int mt = 0; mt < 4; mt++)
#pragma unroll
                for (int nt = 0; nt < 2; nt++)
                    mma_tf32(acc[mt][nt], Af[mt][0], Af[mt][1], Af[mt][2], Af[mt][3],
                             Bf[nt][0], Bf[nt][1]);
        }
    }

#pragma unroll
    for (int mt = 0; mt < 4; mt++) {
#pragma unroll
        for (int nt = 0; nt < 2; nt++) {
            const int row = bm + wm * 64 + mt * 16 + (lane >> 2);
            const int col = bo + wn * 16 + nt * 8 + (lane & 3) * 2;
            float2 v0 = make_float2(acc[mt][nt][0], acc[mt][nt][1]);
            float2 v1 = make_float2(acc[mt][nt][2], acc[mt][nt][3]);
            *reinterpret_cast<__half2*>(&g_h16[row * HF_ + col]) = __float22half2_rn(v0);
            *reinterpret_cast<__half2*>(&g_h16[(row + 8) * HF_ + col]) = __float22half2_rn(v1);
        }
    }

    float asv[2][2], adv[2][2];
#pragma unroll
    for (int nt = 0; nt < 2; nt++)
#pragma unroll
        for (int j = 0; j < 2; j++) {
            const int c = wn * 16 + nt * 8 + (lane & 3) * 2 + j;
            asv[nt][j] = a_src[head * F_ + c];
            adv[nt][j] = a_dst[head * F_ + c];
        }

    __syncthreads();
#pragma unroll
    for (int mt = 0; mt < 4; mt++) {
        float ps0 = 0.f, ps1 = 0.f, pd0 = 0.f, pd1 = 0.f;
#pragma unroll
        for (int nt = 0; nt < 2; nt++) {
            ps0 = fmaf(acc[mt][nt][0], asv[nt][0], ps0);
            ps0 = fmaf(acc[mt][nt][1], asv[nt][1], ps0);
            ps1 = fmaf(acc[mt][nt][2], asv[nt][0], ps1);
            ps1 = fmaf(acc[mt][nt][3], asv[nt][1], ps1);
            pd0 = fmaf(acc[mt][nt][0], adv[nt][0], pd0);
            pd0 = fmaf(acc[mt][nt][1], adv[nt][1], pd0);
            pd1 = fmaf(acc[mt][nt][2], adv[nt][0], pd1);
            pd1 = fmaf(acc[mt][nt][3], adv[nt][1], pd1);
        }
#pragma unroll
        for (int o = 1; o < 4; o <<= 1) {
            ps0 += __shfl_xor_sync(0xFFFFFFFFu, ps0, o);
            ps1 += __shfl_xor_sync(0xFFFFFFFFu, ps1, o);
            pd0 += __shfl_xor_sync(0xFFFFFFFFu, pd0, o);
            pd1 += __shfl_xor_sync(0xFFFFFFFFu, pd1, o);
        }
        if ((lane & 3) == 0) {
            const int r = wm * 64 + mt * 16 + (lane >> 2);
            atomicAdd(&sS[r], ps0);
            atomicAdd(&sS[r + 8], ps1);
            atomicAdd(&sD[r], pd0);
            atomicAdd(&sD[r + 8], pd1);
        }
    }
    __syncthreads();
    if (t < GBM) {
        g_ssrc[(bm + t) * H_ + head] = sS[t];
        g_sdst[(bm + t) * H_ + head] = sD[t];
    }
}

// ---------------------------------------------------------------------------
__device__ __forceinline__ void accum_row(float2& a0, float2& a1, float2& a2, float2& a3,
                                          float p, const uint4& v)
{
    float2 f;
    f = __half22float2(*reinterpret_cast<const __half2*>(&v.x));
    a0.x = fmaf(p, f.x, a0.x); a0.y = fmaf(p, f.y, a0.y);
    f = __half22float2(*reinterpret_cast<const __half2*>(&v.y));
    a1.x = fmaf(p, f.x, a1.x); a1.y = fmaf(p, f.y, a1.y);
    f = __half22float2(*reinterpret_cast<const __half2*>(&v.z));
    a2.x = fmaf(p, f.x, a2.x); a2.y = fmaf(p, f.y, a2.y);
    f = __half22float2(*reinterpret_cast<const __half2*>(&v.w));
    a3.x = fmaf(p, f.x, a3.x); a3.y = fmaf(p, f.y, a3.y);
}

// ---------------------------------------------------------------------------
// Kernel 2 (attn v7): persistent blocks, ticket-fed groups. Same inner
// algorithm as R9 (strided-exp phase 1, MLP-4 gather phase 2).
// ---------------------------------------------------------------------------
#define ATT_NPB 2   // n's per group; 4 warps = {b0,b1} x {n0,n1}

__global__ __launch_bounds__(128, 10) void attn_kernel(float* __restrict__ out)
{
    __shared__ __align__(16) int   nbS[ATT_NPB][MAXD_S];
    __shared__ __align__(16) float pS[4][H_ * PSTR];
    __shared__ int degS[ATT_NPB];
    __shared__ int grpS;

    const int t    = threadIdx.x;
    const int w    = t >> 5;
    const int lane = t & 31;
    const int b    = w & 1;
    const int nsub = w >> 1;

    for (;;) {
        if (t == 0) grpS = atomicAdd(&g_ticket, 1);
        __syncthreads();
        const int grp = grpS;
        if (grp >= NGROUPS) return;

        const int n  = grp * ATT_NPB + nsub;
        const int bn = b * N_ + n;

        if (b == 0) {
            if (lane == 0) degS[nsub] = g_deg[n];
            const int dg = g_deg[n];
            for (int i = lane; i < dg && i < MAXD_S; i += 32)
                nbS[nsub][i] = g_nbrs[n * MAXD + i];
        }
        __syncthreads();

        const int deg  = degS[nsub];
        const int degc = deg < MAXD_S ? deg : MAXD_S;
        const int bN   = b * N_;

        const float4 c4 = *reinterpret_cast<const float4*>(&g_ssrc[bn * H_]);
        const float4* __restrict__ sd4 = reinterpret_cast<const float4*>(g_sdst);

        // ---- phase 1: strided p computation (all heads)
        float4 sum4 = make_float4(0.f, 0.f, 0.f, 0.f);
        for (int i = lane; i < degc; i += 32) {
            const int m = nbS[nsub][i];
            float4 sdv = sd4[bN + m];
            float ex = c4.x + sdv.x, ey = c4.y + sdv.y, ez = c4.z + sdv.z, ew = c4.w + sdv.w;
            ex = fmaxf(ex, 0.2f * ex);
            ey = fmaxf(ey, 0.2f * ey);
            ez = fmaxf(ez, 0.2f * ez);
            ew = fmaxf(ew, 0.2f * ew);
            float px = __expf(ex), py = __expf(ey), pz = __expf(ez), pw = __expf(ew);
            pS[w][0 * PSTR + i] = px;
            pS[w][1 * PSTR + i] = py;
            pS[w][2 * PSTR + i] = pz;
            pS[w][3 * PSTR + i] = pw;
            sum4.x += px; sum4.y += py; sum4.z += pz; sum4.w += pw;
        }
        for (int i = degc + lane; i < deg; i += 32) {
            const int m = g_nbrs[n * MAXD + i];
            float4 sdv = sd4[bN + m];
            float ex = c4.x + sdv.x, ey = c4.y + sdv.y, ez = c4.z + sdv.z, ew = c4.w + sdv.w;
            ex = fmaxf(ex, 0.2f * ex);
            ey = fmaxf(ey, 0.2f * ey);
            ez = fmaxf(ez, 0.2f * ez);
            ew = fmaxf(ew, 0.2f * ew);
            sum4.x += __expf(ex); sum4.y += __expf(ey); sum4.z += __expf(ez); sum4.w += __expf(ew);
        }
#pragma unroll
        for (int o = 16; o > 0; o >>= 1) {
            sum4.x += __shfl_xor_sync(0xFFFFFFFFu, sum4.x, o);
            sum4.y += __shfl_xor_sync(0xFFFFFFFFu, sum4.y, o);
            sum4.z += __shfl_xor_sync(0xFFFFFFFFu, sum4.z, o);
            sum4.w += __shfl_xor_sync(0xFFFFFFFFu, sum4.w, o);
        }

        const int head = lane >> 3;
        float invh = (head & 2) ? ((head & 1) ? sum4.w : sum4.z)
                                : ((head & 1) ? sum4.y : sum4.x);
        invh = 1.0f / invh;

        __syncwarp();

        // ---- phase 2: gather + weighted accumulate, unrolled x4 (MLP 4)
        const uint4* __restrict__ hrow = reinterpret_cast<const uint4*>(g_h16) + (long long)bN * 32 + lane;
        const float* __restrict__ pw = &pS[w][head * PSTR];
        const int*   __restrict__ nbp = &nbS[nsub][0];

        float2 a0 = make_float2(0.f, 0.f), a1 = a0, a2 = a0, a3 = a0;

        int i = 0;
        for (; i + 4 <= degc; i += 4) {
            const int4   mm = *reinterpret_cast<const int4*>(&nbp[i]);
            const float4 pp = *reinterpret_cast<const float4*>(&pw[i]);
            const uint4 v0 = hrow[mm.x * 32];
            const uint4 v1 = hrow[mm.y * 32];
            const uint4 v2 = hrow[mm.z * 32];
            const uint4 v3 = hrow[mm.w * 32];
            accum_row(a0, a1, a2, a3, pp.x, v0);
            accum_row(a0, a1, a2, a3, pp.y, v1);
            accum_row(a0, a1, a2, a3, pp.z, v2);
            accum_row(a0, a1, a2, a3, pp.w, v3);
        }
        for (; i < degc; i++) {
            const float p0 = pw[i];
            const uint4 v0 = hrow[nbp[i] * 32];
            accum_row(a0, a1, a2, a3, p0, v0);
        }
        for (i = degc; i < deg; i++) {
            const int m0 = g_nbrs[n * MAXD + i];
            float4 sdv = sd4[bN + m0];
            float e = ((head & 2) ? ((head & 1) ? c4.w + sdv.w : c4.z + sdv.z)
                                  : ((head & 1) ? c4.y + sdv.y : c4.x + sdv.x));
            e = fmaxf(e, 0.2f * e);
            const float p0 = __expf(e);
            const uint4 v0 = hrow[m0 * 32];
            accum_row(a0, a1, a2, a3, p0, v0);
        }

        float4 o0 = make_float4(a0.x * invh, a0.y * invh, a1.x * invh, a1.y * invh);
        float4 o1 = make_float4(a2.x * invh, a2.y * invh, a3.x * invh, a3.y * invh);
        float4* outp = reinterpret_cast<float4*>(out);
        outp[bn * 64 + lane * 2 + 0] = o0;
        outp[bn * 64 + lane * 2 + 1] = o1;

        __syncthreads();   // smem safe to reuse next iteration
    }
}

// ---------------------------------------------------------------------------
extern "C" void kernel_launch(void* const* d_in, const int* in_sizes, int n_in,
                              void* d_out, int out_size)
{
    const float* x     = (const float*)d_in[0];
    const float* adj   = (const float*)d_in[1];
    const float* W     = (const float*)d_in[2];
    const float* a_src = (const float*)d_in[3];
    const float* a_dst = (const float*)d_in[4];
    float* out = (float*)d_out;

    fused_gemm_csr<<<GEMM_BLOCKS + CSR_BLOCKS, 256>>>(x, W, a_src, a_dst, adj);
    attn_kernel<<<ATT_GRID, 128>>>(out);
}